// round 6
// baseline (speedup 1.0000x reference)
#include <cuda_runtime.h>
#include <cuda_bf16.h>
#include <cstdint>

// ---------------- problem constants ----------------
#define B_    2
#define N_    262144
#define T_    250                     // valid output points per CTA
#define ROWS_ 256                     // buffer rows (halo 3 each side)
#define NTILE ((N_ + T_ - 1) / T_)    // 1049
#define EPS_  1e-5f

// ---------------- smem layout (bytes) ----------------
// 4 activation buffers (ping-pong pairs x {hi,lo}) of 256 rows x 128B, XOR-swizzled
// 2 weight-fragment buffers (double-buffered, prefetched a full layer ahead)
// bias: 3 x 64 floats
#define BUFBYTES  (ROWS_ * 128)            // 32768
#define SM_BUF    0
#define WBYTES    49152                    // 3 taps x 2 parts x 8 nb x 4 kb x 32 lanes x 8B
#define SM_W      (4 * BUFBYTES)           // 131072
#define SM_BIAS   (SM_W + 2 * WBYTES)      // 229376
#define SM_TOTAL  (SM_BIAS + 768)          // 230144  (<= 232448 opt-in)

// ---------------- device globals (no allocs allowed) ----------------
__device__ float   g_tmp[(size_t)B_ * N_ * 64];     // inter-block scratch (128 MB)
__device__ __align__(16) uint32_t g_wfrag[73728];   // [bk][L][t][part][nb][kb][lane][reg]
__device__ float   g_bias[2][192];                  // folded bias [blk][L*64+o]
__device__ int     g_idx64;

// ---------------- helpers ----------------
__device__ __forceinline__ uint32_t smem_u32(const void* p) {
    uint32_t a;
    asm("{ .reg .u64 t; cvta.to.shared.u64 t, %1; cvt.u32.u64 %0, t; }" : "=r"(a) : "l"(p));
    return a;
}
__device__ __forceinline__ uint16_t f2bf(float f) {
    __nv_bfloat16 h = __float2bfloat16_rn(f);
    return *(uint16_t*)&h;
}
__device__ __forceinline__ float bf2f(uint32_t u) {  // low 16 bits = bf16 pattern
    return __uint_as_float((u & 0xFFFFu) << 16);
}
// activation swizzle: row r (0..255), byte col cb (0..127, >=4B aligned)
__device__ __forceinline__ uint32_t aswz(int r, int cb) {
    return (uint32_t)(r * 128 + (cb ^ ((r & 7) * 16)));
}
// pack (v0,v1) -> {hi bf16x2, lo bf16x2} with v0 in the low half
__device__ __forceinline__ uint2 pack2(float v0, float v1) {
    uint32_t h;
    asm("cvt.rn.bf16x2.f32 %0, %1, %2;" : "=r"(h) : "f"(v1), "f"(v0));
    float l0 = v0 - __uint_as_float(h << 16);
    float l1 = v1 - __uint_as_float(h & 0xFFFF0000u);
    uint32_t l;
    asm("cvt.rn.bf16x2.f32 %0, %1, %2;" : "=r"(l) : "f"(l1), "f"(l0));
    return make_uint2(h, l);
}

__device__ __forceinline__ void mma_bf16(float d[4], const uint32_t a[4],
                                         uint32_t b0, uint32_t b1) {
    asm volatile(
        "mma.sync.aligned.m16n8k16.row.col.f32.bf16.bf16.f32 "
        "{%0,%1,%2,%3}, {%4,%5,%6,%7}, {%8,%9}, {%0,%1,%2,%3};"
        : "+f"(d[0]), "+f"(d[1]), "+f"(d[2]), "+f"(d[3])
        : "r"(a[0]), "r"(a[1]), "r"(a[2]), "r"(a[3]), "r"(b0), "r"(b1));
}

#define LDSM4(a, addr)                                                         \
    asm volatile("ldmatrix.sync.aligned.m8n8.x4.shared.b16 {%0,%1,%2,%3}, [%4];" \
        : "=r"((a)[0]), "=r"((a)[1]), "=r"((a)[2]), "=r"((a)[3]) : "r"(addr))

#define CPA16(dst, src)                                                        \
    asm volatile("cp.async.cg.shared.global [%0], [%1], 16;"                   \
        :: "r"(dst), "l"(src) : "memory")
#define CPA_COMMIT() asm volatile("cp.async.commit_group;" ::: "memory")
#define CPA_WAIT0()  asm volatile("cp.async.wait_group 0;" ::: "memory")

// ---------------------------------------------------------------------------
// Prep: fold BN into conv weights, split bf16 hi/lo, emit mma.sync B-fragments
// in final lane/register layout; fold bias; detect index dtype.
// ---------------------------------------------------------------------------
__global__ void prep_kernel(const float* __restrict__ conv_w,
                            const float* __restrict__ bg,
                            const float* __restrict__ bb,
                            const float* __restrict__ bm,
                            const float* __restrict__ bv,
                            const void*  __restrict__ pa1)
{
    int idx = blockIdx.x * blockDim.x + threadIdx.x;

    if (idx == 0) {
        const int* p = (const int*)pa1;   // int64 perm -> zero high words
        g_idx64 = (p[1] == 0 && p[3] == 0 && p[5] == 0 && p[7] == 0) ? 1 : 0;
    }
    if (idx < 384) {                      // bias fold [bk][L][o]
        int o = idx & 63, L = (idx >> 6) % 3, bk = idx / 192;
        float sc = bg[idx] * rsqrtf(bv[idx] + EPS_);
        g_bias[bk][L * 64 + o] = bb[idx] - bm[idx] * sc;
    }
    if (idx < 73728) {
        int q = idx;
        int reg  = q & 1;  q >>= 1;
        int lane = q & 31; q >>= 5;
        int kb   = q & 3;  q >>= 2;
        int nb   = q & 7;  q >>= 3;
        int part = q & 1;  q >>= 1;
        int t    = q % 3;  q /= 3;
        int L    = q % 3;
        int bk   = q / 3;

        int n  = nb * 8 + (lane >> 2);                 // output channel
        int k0 = kb * 16 + reg * 8 + (lane & 3) * 2;   // input channel pair
        int bni = (bk * 3 + L) * 64 + n;
        float sc = bg[bni] * rsqrtf(bv[bni] + EPS_);

        uint16_t hv[2];
        #pragma unroll
        for (int h = 0; h < 2; ++h) {
            int i = k0 + h;
            float w = conv_w[(((size_t)(bk * 3 + L) * 64 + n) * 64 + i) * 3 + t] * sc;
            uint16_t hi = f2bf(w);
            hv[h] = (part == 0) ? hi : f2bf(w - bf2f(hi));
        }
        g_wfrag[idx] = (uint32_t)hv[0] | ((uint32_t)hv[1] << 16);
    }
}

// ---------------------------------------------------------------------------
// Fused block: gather -> 3 x (mma.sync conv + BN + act) -> residual -> scatter
// One CTA = 250 output points (256-row swizzled buffers), 256 threads,
// 8 warps x M=32. Weights double-buffered, prefetched one layer ahead.
// ---------------------------------------------------------------------------
__global__ void __launch_bounds__(256, 1)
mc_block_kernel(const float* __restrict__ xin,
                const void*  __restrict__ pav,
                float* __restrict__ out,
                int bk)
{
    extern __shared__ uint8_t smem[];
    const uint32_t sbase = smem_u32(smem);
    const int tid = threadIdx.x, wid = tid >> 5, lane = tid & 31;
    const int b = blockIdx.y;
    const int ts = blockIdx.x * T_;
    const bool is64 = (g_idx64 != 0);
    const int*       pa32 = (const int*)pav;
    const long long* pa64 = (const long long*)pav;

    if (tid < 192) ((float*)(smem + SM_BIAS))[tid] = g_bias[bk][tid];

    // ---- stage layer-0 weight fragments into buffer 0 (overlaps gather) ----
    {
        const uint8_t* src = (const uint8_t*)g_wfrag + (size_t)(bk * 3) * WBYTES;
        #pragma unroll
        for (int i = 0; i < 12; ++i) {
            int e = tid + i * 256;
            CPA16(sbase + SM_W + e * 16, src + (size_t)e * 16);
        }
        CPA_COMMIT();
    }

    // ---- gather 256 rows (points ts-3 .. ts+252) into pair0, bf16 hi/lo ----
    {
        const int r = tid;                 // one thread per row
        int gp = ts - 3 + r;
        bool ok = (gp >= 0) && (gp < N_);
        const float4* src = nullptr;
        if (ok) {
            long long prow = is64 ? pa64[(size_t)b * N_ + gp]
                                  : (long long)pa32[(size_t)b * N_ + gp];
            src = (const float4*)(xin + ((size_t)b * N_ + (size_t)prow) * 64);
        }
        uint8_t* bh0 = smem + SM_BUF;              // pair0 hi
        uint8_t* bl0 = bh0 + BUFBYTES;             // pair0 lo
        const int rot = (r >> 3) & 15;             // column rotation kills ST conflicts
        #pragma unroll
        for (int w2 = 0; w2 < 2; ++w2) {           // two waves of 8 batched loads
            int ie[8];
            float4 v[8];
            #pragma unroll
            for (int i = 0; i < 8; ++i) {
                ie[i] = (w2 * 8 + i + rot) & 15;
                v[i] = ok ? src[ie[i]] : make_float4(0.f, 0.f, 0.f, 0.f);
            }
            #pragma unroll
            for (int i = 0; i < 8; ++i) {
                uint2 p01 = pack2(v[i].x, v[i].y);
                uint2 p23 = pack2(v[i].z, v[i].w);
                uint32_t off = aswz(r, ie[i] * 8);
                *(uint2*)(bh0 + off) = make_uint2(p01.x, p23.x);
                *(uint2*)(bl0 + off) = make_uint2(p01.y, p23.y);
            }
        }
    }

    // A-operand ldmatrix row bases + swizzle keys: [slab][tap]
    uint32_t arow[2][3], akey[2][3];
    #pragma unroll
    for (int s2 = 0; s2 < 2; ++s2)
        #pragma unroll
        for (int t = 0; t < 3; ++t) {
            int rr = wid * 32 + s2 * 16 + t - 1 + (lane & 15);
            rr = rr < 0 ? 0 : (rr > 255 ? 255 : rr);
            arow[s2][t] = (uint32_t)(rr * 128);
            akey[s2][t] = (uint32_t)((rr & 7) * 16);
        }
    const uint32_t half16 = (uint32_t)((lane >> 4) * 16);

    #pragma unroll
    for (int L = 0; L < 3; ++L) {
        CPA_WAIT0();          // this layer's weights landed (prefetched earlier)
        __syncthreads();      // weights + prev epilogue/gather visible

        // prefetch NEXT layer's weights into the other buffer (hides under MMA)
        if (L < 2) {
            const uint8_t* src = (const uint8_t*)g_wfrag + (size_t)(bk * 3 + L + 1) * WBYTES;
            uint32_t dst = sbase + SM_W + (uint32_t)(((L + 1) & 1) * WBYTES);
            #pragma unroll
            for (int i = 0; i < 12; ++i) {
                int e = tid + i * 256;
                CPA16(dst + e * 16, src + (size_t)e * 16);
            }
            CPA_COMMIT();
        }

        const int inp = (L == 1) ? 1 : 0;          // L0:p0, L1:p1, L2:p0
        const uint32_t inHi = sbase + SM_BUF + (uint32_t)(inp * 2) * BUFBYTES;
        const uint32_t inLo = inHi + BUFBYTES;
        const uint8_t* wl = smem + SM_W + (size_t)((L & 1) * WBYTES) + lane * 8;

        // final layer: preload scatter rows + prefetch residual x into L2
        long long prow_s[4];
        if (L == 2) {
            #pragma unroll
            for (int s2 = 0; s2 < 2; ++s2)
                #pragma unroll
                for (int rh = 0; rh < 2; ++rh) {
                    const int r = wid * 32 + s2 * 16 + rh * 8 + (lane >> 2);
                    const int gp = ts - 3 + r;
                    const bool ok = (r >= 3) && (r <= 252) && (gp < N_);
                    int gpc = ok ? gp : 0;
                    long long prow = is64 ? pa64[(size_t)b * N_ + gpc]
                                          : (long long)pa32[(size_t)b * N_ + gpc];
                    prow_s[s2 * 2 + rh] = prow;
                    if (ok) {
                        const char* xp = (const char*)(xin + ((size_t)b * N_ + (size_t)prow) * 64)
                                       + (lane & 3) * 64;
                        asm volatile("prefetch.global.L2 [%0];" :: "l"(xp));
                    }
                }
        }

        float d[2][8][4];
        #pragma unroll
        for (int s2 = 0; s2 < 2; ++s2)
            #pragma unroll
            for (int nb = 0; nb < 8; ++nb)
                #pragma unroll
                for (int j = 0; j < 4; ++j) d[s2][nb][j] = 0.f;

        #pragma unroll
        for (int t = 0; t < 3; ++t) {
            #pragma unroll
            for (int kb = 0; kb < 4; ++kb) {
                const uint32_t colc = half16 + (uint32_t)(kb * 32);
                uint32_t a0[4], a1[4];
                LDSM4(a0, inHi + arow[0][t] + (colc ^ akey[0][t]));
                LDSM4(a1, inHi + arow[1][t] + (colc ^ akey[1][t]));

                uint2 bh[8];
                #pragma unroll
                for (int nb = 0; nb < 8; ++nb) {       // A_hi * B_hi
                    bh[nb] = *(const uint2*)(wl + (size_t)((((t * 2 + 0) * 8 + nb) * 4 + kb) * 256));
                    mma_bf16(d[0][nb], a0, bh[nb].x, bh[nb].y);
                    mma_bf16(d[1][nb], a1, bh[nb].x, bh[nb].y);
                }
                #pragma unroll
                for (int nb = 0; nb < 8; ++nb) {       // A_hi * B_lo
                    uint2 bl = *(const uint2*)(wl + (size_t)((((t * 2 + 1) * 8 + nb) * 4 + kb) * 256));
                    mma_bf16(d[0][nb], a0, bl.x, bl.y);
                    mma_bf16(d[1][nb], a1, bl.x, bl.y);
                }
                LDSM4(a0, inLo + arow[0][t] + (colc ^ akey[0][t]));
                LDSM4(a1, inLo + arow[1][t] + (colc ^ akey[1][t]));
                #pragma unroll
                for (int nb = 0; nb < 8; ++nb) {       // A_lo * B_hi
                    mma_bf16(d[0][nb], a0, bh[nb].x, bh[nb].y);
                    mma_bf16(d[1][nb], a1, bh[nb].x, bh[nb].y);
                }
            }
        }

        // ---- epilogue ----
        const float* bias = (const float*)(smem + SM_BIAS) + L * 64;

        if (L < 2) {
            const int outp = (L == 0) ? 1 : 0;
            uint8_t* oh = smem + SM_BUF + (uint32_t)(outp * 2) * BUFBYTES;
            uint8_t* ol = oh + BUFBYTES;
            #pragma unroll
            for (int s2 = 0; s2 < 2; ++s2) {
                #pragma unroll
                for (int rh = 0; rh < 2; ++rh) {
                    const int r = wid * 32 + s2 * 16 + rh * 8 + (lane >> 2);
                    const int gp = ts - 3 + r;
                    const bool valid = (r >= L + 1) && (r <= 254 - L) && (gp >= 0) && (gp < N_);
                    #pragma unroll
                    for (int nb = 0; nb < 8; ++nb) {
                        const int c0 = nb * 8 + (lane & 3) * 2;
                        float v0 = valid ? fmaxf(d[s2][nb][rh * 2 + 0] + bias[c0], 0.f) : 0.f;
                        float v1 = valid ? fmaxf(d[s2][nb][rh * 2 + 1] + bias[c0 + 1], 0.f) : 0.f;
                        uint2 p = pack2(v0, v1);
                        uint32_t off = aswz(r, c0 * 2);
                        *(uint32_t*)(oh + off) = p.x;
                        *(uint32_t*)(ol + off) = p.y;
                    }
                }
            }
        } else {
            // residual (prefetched) + ReLU + permuted scatter
            #pragma unroll
            for (int s2 = 0; s2 < 2; ++s2) {
                #pragma unroll
                for (int rh = 0; rh < 2; ++rh) {
                    const int r = wid * 32 + s2 * 16 + rh * 8 + (lane >> 2);
                    const int gp = ts - 3 + r;
                    if (r >= 3 && r <= 252 && gp < N_) {
                        long long prow = prow_s[s2 * 2 + rh];
                        const float* xp = xin + ((size_t)b * N_ + (size_t)prow) * 64;
                        float* op = out + ((size_t)b * N_ + (size_t)prow) * 64;
                        #pragma unroll
                        for (int nb = 0; nb < 8; ++nb) {
                            const int c0 = nb * 8 + (lane & 3) * 2;
                            float2 xv = *(const float2*)(xp + c0);
                            float2 o2;
                            o2.x = fmaxf(xv.x + d[s2][nb][rh * 2 + 0] + bias[c0], 0.f);
                            o2.y = fmaxf(xv.y + d[s2][nb][rh * 2 + 1] + bias[c0 + 1], 0.f);
                            *(float2*)(op + c0) = o2;
                        }
                    }
                }
            }
        }
    }
}

// ---------------------------------------------------------------------------
extern "C" void kernel_launch(void* const* d_in, const int* in_sizes, int n_in,
                              void* d_out, int out_size)
{
    const float* x      = (const float*)d_in[0];
    const void*  pa1    = d_in[1];
    // d_in[2] = idx_re_1 (unused: re ∘ pa = id, scatter uses pa)
    const void*  pa2    = d_in[3];
    // d_in[4] = idx_re_2 (unused)
    const float* conv_w = (const float*)d_in[5];
    const float* bg     = (const float*)d_in[6];
    const float* bb     = (const float*)d_in[7];
    const float* bm     = (const float*)d_in[8];
    const float* bv     = (const float*)d_in[9];
    float* out = (float*)d_out;

    cudaFuncSetAttribute(mc_block_kernel,
                         cudaFuncAttributeMaxDynamicSharedMemorySize, SM_TOTAL);

    void* tmpp = nullptr;
    cudaGetSymbolAddress(&tmpp, g_tmp);

    prep_kernel<<<(73728 + 255) / 256, 256>>>(conv_w, bg, bb, bm, bv, pa1);

    dim3 grid(NTILE, B_);
    mc_block_kernel<<<grid, 256, SM_TOTAL>>>(x, pa1, (float*)tmpp, 0);
    mc_block_kernel<<<grid, 256, SM_TOTAL>>>((const float*)tmpp, pa2, out, 1);
}

// round 7
// speedup vs baseline: 1.5987x; 1.5987x over previous
#include <cuda_runtime.h>
#include <cuda_bf16.h>
#include <cstdint>

// ---------------- problem constants ----------------
#define B_    2
#define N_    262144
#define T_    250                     // valid output points per CTA
#define ROWS_ 256                     // buffer rows (halo 3 each side)
#define NTILE ((N_ + T_ - 1) / T_)    // 1049
#define EPS_  1e-5f

// ---------------- smem layout (bytes) ----------------
// 4 activation buffers (ping-pong pairs x {hi,lo}) of 256 rows x 144B
// 1 weight-fragment buffer 48KB x2 slots? NO: single 48KB stage (re-staged per layer)
// bias: 3 x 64 floats.  Total kept < 200KB so ~30KB L1D survives.
#define ROWSTRIDE 144
#define BUFBYTES  (ROWS_ * ROWSTRIDE)      // 36864
#define SM_BUF    0
#define WBYTES    49152                    // 3 taps x 2 parts x 8 nb x 4 kb x 32 lanes x 8B
#define SM_W      (4 * BUFBYTES)           // 147456
#define SM_BIAS   (SM_W + WBYTES)          // 196608
#define SM_TOTAL  (SM_BIAS + 1024)         // 197632

// ---------------- device globals (no allocs allowed) ----------------
__device__ float   g_tmp[(size_t)B_ * N_ * 64];     // inter-block scratch (128 MB)
__device__ __align__(16) uint32_t g_wfrag[73728];   // [bk][L][t][part][nb][kb][lane][reg]
__device__ float   g_bias[2][192];                  // folded bias [blk][L*64+o]
__device__ int     g_idx64;

// ---------------- helpers ----------------
__device__ __forceinline__ uint32_t smem_u32(const void* p) {
    uint32_t a;
    asm("{ .reg .u64 t; cvta.to.shared.u64 t, %1; cvt.u32.u64 %0, t; }" : "=r"(a) : "l"(p));
    return a;
}
__device__ __forceinline__ uint16_t f2bf(float f) {
    __nv_bfloat16 h = __float2bfloat16_rn(f);
    return *(uint16_t*)&h;
}
__device__ __forceinline__ float bf2f(uint32_t u) {  // low 16 bits = bf16 pattern
    return __uint_as_float((u & 0xFFFFu) << 16);
}
// pack (v0,v1) -> {hi bf16x2, lo bf16x2} with v0 in the low half
__device__ __forceinline__ uint2 pack2(float v0, float v1) {
    uint32_t h;
    asm("cvt.rn.bf16x2.f32 %0, %1, %2;" : "=r"(h) : "f"(v1), "f"(v0));
    float l0 = v0 - __uint_as_float(h << 16);
    float l1 = v1 - __uint_as_float(h & 0xFFFF0000u);
    uint32_t l;
    asm("cvt.rn.bf16x2.f32 %0, %1, %2;" : "=r"(l) : "f"(l1), "f"(l0));
    return make_uint2(h, l);
}

__device__ __forceinline__ void mma_bf16(float d[4], const uint32_t a[4],
                                         uint32_t b0, uint32_t b1) {
    asm volatile(
        "mma.sync.aligned.m16n8k16.row.col.f32.bf16.bf16.f32 "
        "{%0,%1,%2,%3}, {%4,%5,%6,%7}, {%8,%9}, {%0,%1,%2,%3};"
        : "+f"(d[0]), "+f"(d[1]), "+f"(d[2]), "+f"(d[3])
        : "r"(a[0]), "r"(a[1]), "r"(a[2]), "r"(a[3]), "r"(b0), "r"(b1));
}

#define LDSM4(a, addr)                                                         \
    asm volatile("ldmatrix.sync.aligned.m8n8.x4.shared.b16 {%0,%1,%2,%3}, [%4];" \
        : "=r"((a)[0]), "=r"((a)[1]), "=r"((a)[2]), "=r"((a)[3]) : "r"(addr))

#define CPA16(dst, src)                                                        \
    asm volatile("cp.async.cg.shared.global [%0], [%1], 16;"                   \
        :: "r"(dst), "l"(src) : "memory")
#define CPA_COMMIT() asm volatile("cp.async.commit_group;" ::: "memory")
#define CPA_WAIT0()  asm volatile("cp.async.wait_group 0;" ::: "memory")

// ---------------------------------------------------------------------------
// Prep: fold BN into conv weights, split bf16 hi/lo, emit mma.sync B-fragments
// in final lane/register layout; fold bias; detect index dtype.
// ---------------------------------------------------------------------------
__global__ void prep_kernel(const float* __restrict__ conv_w,
                            const float* __restrict__ bg,
                            const float* __restrict__ bb,
                            const float* __restrict__ bm,
                            const float* __restrict__ bv,
                            const void*  __restrict__ pa1)
{
    int idx = blockIdx.x * blockDim.x + threadIdx.x;

    if (idx == 0) {
        const int* p = (const int*)pa1;   // int64 perm -> zero high words
        g_idx64 = (p[1] == 0 && p[3] == 0 && p[5] == 0 && p[7] == 0) ? 1 : 0;
    }
    if (idx < 384) {                      // bias fold [bk][L][o]
        int o = idx & 63, L = (idx >> 6) % 3, bk = idx / 192;
        float sc = bg[idx] * rsqrtf(bv[idx] + EPS_);
        g_bias[bk][L * 64 + o] = bb[idx] - bm[idx] * sc;
    }
    if (idx < 73728) {
        int q = idx;
        int reg  = q & 1;  q >>= 1;
        int lane = q & 31; q >>= 5;
        int kb   = q & 3;  q >>= 2;
        int nb   = q & 7;  q >>= 3;
        int part = q & 1;  q >>= 1;
        int t    = q % 3;  q /= 3;
        int L    = q % 3;
        int bk   = q / 3;

        int n  = nb * 8 + (lane >> 2);                 // output channel
        int k0 = kb * 16 + reg * 8 + (lane & 3) * 2;   // input channel pair
        int bni = (bk * 3 + L) * 64 + n;
        float sc = bg[bni] * rsqrtf(bv[bni] + EPS_);

        uint16_t hv[2];
        #pragma unroll
        for (int h = 0; h < 2; ++h) {
            int i = k0 + h;
            float w = conv_w[(((size_t)(bk * 3 + L) * 64 + n) * 64 + i) * 3 + t] * sc;
            uint16_t hi = f2bf(w);
            hv[h] = (part == 0) ? hi : f2bf(w - bf2f(hi));
        }
        g_wfrag[idx] = (uint32_t)hv[0] | ((uint32_t)hv[1] << 16);
    }
}

// ---------------------------------------------------------------------------
// Fused block: gather -> 3 x (mma.sync conv + BN + act) -> residual -> scatter
// One CTA = 250 output points (256-row buffer), 256 threads, 8 warps x M=32.
// ---------------------------------------------------------------------------
__global__ void __launch_bounds__(256, 1)
mc_block_kernel(const float* __restrict__ xin,
                const void*  __restrict__ pav,
                float* __restrict__ out,
                int bk)
{
    extern __shared__ uint8_t smem[];
    const uint32_t sbase = smem_u32(smem);
    const int tid = threadIdx.x, wid = tid >> 5, lane = tid & 31;
    const int b = blockIdx.y;
    const int ts = blockIdx.x * T_;
    const bool is64 = (g_idx64 != 0);
    const int*       pa32 = (const int*)pav;
    const long long* pa64 = (const long long*)pav;

    if (tid < 192) ((float*)(smem + SM_BIAS))[tid] = g_bias[bk][tid];

    // ---- stage layer-0 weight fragments (48KB) via cp.async (overlaps gather) ----
    {
        const uint8_t* src = (const uint8_t*)g_wfrag + (size_t)(bk * 3) * WBYTES;
        #pragma unroll
        for (int i = 0; i < 12; ++i) {
            int e = tid + i * 256;
            CPA16(sbase + SM_W + e * 16, src + (size_t)e * 16);
        }
        CPA_COMMIT();
    }

    // ---- gather 256 rows (points ts-3 .. ts+252) into pair0, bf16 hi/lo ----
    {
        const int r = tid;                 // one thread per row
        int gp = ts - 3 + r;
        bool ok = (gp >= 0) && (gp < N_);
        const float4* src = nullptr;
        if (ok) {
            long long prow = is64 ? pa64[(size_t)b * N_ + gp]
                                  : (long long)pa32[(size_t)b * N_ + gp];
            src = (const float4*)(xin + ((size_t)b * N_ + (size_t)prow) * 64);
        }
        uint8_t* bh0 = smem + SM_BUF;              // pair0 hi
        uint8_t* bl0 = bh0 + BUFBYTES;             // pair0 lo
        #pragma unroll
        for (int w2 = 0; w2 < 2; ++w2) {           // two waves of 8 batched loads
            float4 v[8];
            #pragma unroll
            for (int i = 0; i < 8; ++i)
                v[i] = ok ? src[w2 * 8 + i] : make_float4(0.f, 0.f, 0.f, 0.f);
            #pragma unroll
            for (int i = 0; i < 8; ++i) {
                uint2 p01 = pack2(v[i].x, v[i].y);
                uint2 p23 = pack2(v[i].z, v[i].w);
                uint32_t off = (uint32_t)(r * ROWSTRIDE + (w2 * 8 + i) * 8);
                *(uint2*)(bh0 + off) = make_uint2(p01.x, p23.x);
                *(uint2*)(bl0 + off) = make_uint2(p01.y, p23.y);
            }
        }
    }

    CPA_WAIT0();
    __syncthreads();

    // A-operand ldmatrix row offsets: [slab][tap], rows clamped to [0,255]
    uint32_t aoff[2][3];
    #pragma unroll
    for (int s2 = 0; s2 < 2; ++s2)
        #pragma unroll
        for (int t = 0; t < 3; ++t) {
            int rr = wid * 32 + s2 * 16 + t - 1 + (lane & 15);
            rr = rr < 0 ? 0 : (rr > 255 ? 255 : rr);
            aoff[s2][t] = (uint32_t)(rr * ROWSTRIDE) + ((lane >> 4) * 16);
        }

    #pragma unroll
    for (int L = 0; L < 3; ++L) {
        const int inp = (L == 1) ? 1 : 0;          // L0:p0, L1:p1, L2:p0
        const uint32_t inHi = sbase + SM_BUF + (uint32_t)(inp * 2) * BUFBYTES;
        const uint32_t inLo = inHi + BUFBYTES;
        const uint8_t* wl = smem + SM_W + lane * 8;

        // final layer: preload scatter rows + prefetch residual x into L2
        long long prow_s[4];
        if (L == 2) {
            #pragma unroll
            for (int s2 = 0; s2 < 2; ++s2)
                #pragma unroll
                for (int rh = 0; rh < 2; ++rh) {
                    const int r = wid * 32 + s2 * 16 + rh * 8 + (lane >> 2);
                    const int gp = ts - 3 + r;
                    const bool okr = (r >= 3) && (r <= 252) && (gp < N_);
                    int gpc = okr ? gp : 0;
                    long long prow = is64 ? pa64[(size_t)b * N_ + gpc]
                                          : (long long)pa32[(size_t)b * N_ + gpc];
                    prow_s[s2 * 2 + rh] = prow;
                    if (okr) {
                        const char* xp = (const char*)(xin + ((size_t)b * N_ + (size_t)prow) * 64)
                                       + (lane & 3) * 64;
                        asm volatile("prefetch.global.L2 [%0];" :: "l"(xp));
                    }
                }
        }

        float d[2][8][4];
        #pragma unroll
        for (int s2 = 0; s2 < 2; ++s2)
            #pragma unroll
            for (int nb = 0; nb < 8; ++nb)
                #pragma unroll
                for (int j = 0; j < 4; ++j) d[s2][nb][j] = 0.f;

        #pragma unroll
        for (int t = 0; t < 3; ++t) {
            #pragma unroll
            for (int kb = 0; kb < 4; ++kb) {
                // front-batch ALL four A-fragment loads (hi+lo, both slabs)
                uint32_t a0[4], a1[4], c0[4], c1[4];
                LDSM4(a0, inHi + aoff[0][t] + kb * 32);
                LDSM4(a1, inHi + aoff[1][t] + kb * 32);
                LDSM4(c0, inLo + aoff[0][t] + kb * 32);
                LDSM4(c1, inLo + aoff[1][t] + kb * 32);

                uint2 bh[8];
                #pragma unroll
                for (int nb = 0; nb < 8; ++nb) {       // A_hi * B_hi
                    bh[nb] = *(const uint2*)(wl + (size_t)((((t * 2 + 0) * 8 + nb) * 4 + kb) * 256));
                    mma_bf16(d[0][nb], a0, bh[nb].x, bh[nb].y);
                    mma_bf16(d[1][nb], a1, bh[nb].x, bh[nb].y);
                }
                #pragma unroll
                for (int nb = 0; nb < 8; ++nb) {       // A_hi * B_lo
                    uint2 bl = *(const uint2*)(wl + (size_t)((((t * 2 + 1) * 8 + nb) * 4 + kb) * 256));
                    mma_bf16(d[0][nb], a0, bl.x, bl.y);
                    mma_bf16(d[1][nb], a1, bl.x, bl.y);
                }
                #pragma unroll
                for (int nb = 0; nb < 8; ++nb) {       // A_lo * B_hi
                    mma_bf16(d[0][nb], c0, bh[nb].x, bh[nb].y);
                    mma_bf16(d[1][nb], c1, bh[nb].x, bh[nb].y);
                }
            }
        }

        // ---- issue next layer's weight stage BEFORE epilogue (hides xfer) ----
        // Safe: weight buffer's last readers (this layer's MMAs) are this warp
        // (done above) and other warps, which all passed the layer-entry sync
        // before we could reach the post-epilogue sync below.
        if (L < 2) {
            const uint8_t* src = (const uint8_t*)g_wfrag + (size_t)(bk * 3 + L + 1) * WBYTES;
            #pragma unroll
            for (int i = 0; i < 12; ++i) {
                int e = tid + i * 256;
                CPA16(sbase + SM_W + e * 16, src + (size_t)e * 16);
            }
            CPA_COMMIT();
        }

        // ---- epilogue ----
        const float* bias = (const float*)(smem + SM_BIAS) + L * 64;

        if (L < 2) {
            const int outp = (L == 0) ? 1 : 0;
            uint8_t* oh = smem + SM_BUF + (uint32_t)(outp * 2) * BUFBYTES;
            uint8_t* ol = oh + BUFBYTES;
            #pragma unroll
            for (int s2 = 0; s2 < 2; ++s2) {
                #pragma unroll
                for (int rh = 0; rh < 2; ++rh) {
                    const int r = wid * 32 + s2 * 16 + rh * 8 + (lane >> 2);
                    const int gp = ts - 3 + r;
                    const bool valid = (r >= L + 1) && (r <= 254 - L) && (gp >= 0) && (gp < N_);
                    #pragma unroll
                    for (int nb = 0; nb < 8; ++nb) {
                        const int c0i = nb * 8 + (lane & 3) * 2;
                        float v0 = valid ? fmaxf(d[s2][nb][rh * 2 + 0] + bias[c0i], 0.f) : 0.f;
                        float v1 = valid ? fmaxf(d[s2][nb][rh * 2 + 1] + bias[c0i + 1], 0.f) : 0.f;
                        uint2 p = pack2(v0, v1);
                        uint32_t off = (uint32_t)(r * ROWSTRIDE + c0i * 2);
                        *(uint32_t*)(oh + off) = p.x;
                        *(uint32_t*)(ol + off) = p.y;
                    }
                }
            }
            CPA_WAIT0();         // weights for next layer landed (mostly hidden)
            __syncthreads();     // weights + epilogue visible to all
        } else {
            // residual (preloaded rows, L2-prefetched) + ReLU + permuted scatter
            #pragma unroll
            for (int s2 = 0; s2 < 2; ++s2) {
                #pragma unroll
                for (int rh = 0; rh < 2; ++rh) {
                    const int r = wid * 32 + s2 * 16 + rh * 8 + (lane >> 2);
                    const int gp = ts - 3 + r;
                    if (r >= 3 && r <= 252 && gp < N_) {
                        long long prow = prow_s[s2 * 2 + rh];
                        const float* xp = xin + ((size_t)b * N_ + (size_t)prow) * 64;
                        float* op = out + ((size_t)b * N_ + (size_t)prow) * 64;
                        #pragma unroll
                        for (int nb = 0; nb < 8; ++nb) {
                            const int c0i = nb * 8 + (lane & 3) * 2;
                            float2 xv = *(const float2*)(xp + c0i);
                            float2 o2;
                            o2.x = fmaxf(xv.x + d[s2][nb][rh * 2 + 0] + bias[c0i], 0.f);
                            o2.y = fmaxf(xv.y + d[s2][nb][rh * 2 + 1] + bias[c0i + 1], 0.f);
                            *(float2*)(op + c0i) = o2;
                        }
                    }
                }
            }
        }
    }
}

// ---------------------------------------------------------------------------
extern "C" void kernel_launch(void* const* d_in, const int* in_sizes, int n_in,
                              void* d_out, int out_size)
{
    const float* x      = (const float*)d_in[0];
    const void*  pa1    = d_in[1];
    // d_in[2] = idx_re_1 (unused: re ∘ pa = id, scatter uses pa)
    const void*  pa2    = d_in[3];
    // d_in[4] = idx_re_2 (unused)
    const float* conv_w = (const float*)d_in[5];
    const float* bg     = (const float*)d_in[6];
    const float* bb     = (const float*)d_in[7];
    const float* bm     = (const float*)d_in[8];
    const float* bv     = (const float*)d_in[9];
    float* out = (float*)d_out;

    cudaFuncSetAttribute(mc_block_kernel,
                         cudaFuncAttributeMaxDynamicSharedMemorySize, SM_TOTAL);

    void* tmpp = nullptr;
    cudaGetSymbolAddress(&tmpp, g_tmp);

    prep_kernel<<<(73728 + 255) / 256, 256>>>(conv_w, bg, bb, bm, bv, pa1);

    dim3 grid(NTILE, B_);
    mc_block_kernel<<<grid, 256, SM_TOTAL>>>(x, pa1, (float*)tmpp, 0);
    mc_block_kernel<<<grid, 256, SM_TOTAL>>>((const float*)tmpp, pa2, out, 1);
}

// round 8
// speedup vs baseline: 2.2473x; 1.4056x over previous
#include <cuda_runtime.h>
#include <cuda_fp16.h>
#include <cstdint>

// ---------------- problem constants ----------------
#define B_    2
#define N_    262144
#define T_    250                     // valid output points per CTA
#define ROWS_ 256                     // buffer rows (halo 3 each side)
#define NTILE ((N_ + T_ - 1) / T_)    // 1049
#define EPS_  1e-5f

// ---------------- smem layout (bytes) ----------------
// 4 activation buffers (ping-pong pairs x {hi,lo}) of 256 rows x 144B (fp16)
// 1 weight-fragment buffer 24KB (single fp16 weights, re-staged per layer)
// bias: 3 x 64 floats.  Total 173KB -> ~55KB L1D survives.
#define ROWSTRIDE 144
#define BUFBYTES  (ROWS_ * ROWSTRIDE)      // 36864
#define SM_BUF    0
#define WBYTES    24576                    // 3 taps x 8 nb x 4 kb x 32 lanes x 8B
#define SM_W      (4 * BUFBYTES)           // 147456
#define SM_BIAS   (SM_W + WBYTES)          // 172032
#define SM_TOTAL  (SM_BIAS + 1024)         // 173056

// ---------------- device globals (no allocs allowed) ----------------
__device__ float   g_tmp[(size_t)B_ * N_ * 64];     // inter-block scratch (128 MB)
__device__ __align__(16) uint32_t g_wfrag[36864];   // [bk][L][t][nb][kb][lane][reg] fp16x2
__device__ float   g_bias[2][192];                  // folded bias [blk][L*64+o]
__device__ int     g_idx64;

// ---------------- helpers ----------------
__device__ __forceinline__ uint32_t smem_u32(const void* p) {
    uint32_t a;
    asm("{ .reg .u64 t; cvta.to.shared.u64 t, %1; cvt.u32.u64 %0, t; }" : "=r"(a) : "l"(p));
    return a;
}
// pack (v0,v1) -> {hi fp16x2, lo fp16x2} with v0 in the low half
__device__ __forceinline__ uint2 pack2h(float v0, float v1) {
    __half2 h = __floats2half2_rn(v0, v1);
    float l0 = v0 - __low2float(h);
    float l1 = v1 - __high2float(h);
    __half2 l = __floats2half2_rn(l0, l1);
    return make_uint2(*(uint32_t*)&h, *(uint32_t*)&l);
}

__device__ __forceinline__ void mma_f16(float d[4], const uint32_t a[4],
                                        uint32_t b0, uint32_t b1) {
    asm volatile(
        "mma.sync.aligned.m16n8k16.row.col.f32.f16.f16.f32 "
        "{%0,%1,%2,%3}, {%4,%5,%6,%7}, {%8,%9}, {%0,%1,%2,%3};"
        : "+f"(d[0]), "+f"(d[1]), "+f"(d[2]), "+f"(d[3])
        : "r"(a[0]), "r"(a[1]), "r"(a[2]), "r"(a[3]), "r"(b0), "r"(b1));
}

#define LDSM4(a, addr)                                                         \
    asm volatile("ldmatrix.sync.aligned.m8n8.x4.shared.b16 {%0,%1,%2,%3}, [%4];" \
        : "=r"((a)[0]), "=r"((a)[1]), "=r"((a)[2]), "=r"((a)[3]) : "r"(addr))

#define CPA16(dst, src)                                                        \
    asm volatile("cp.async.cg.shared.global [%0], [%1], 16;"                   \
        :: "r"(dst), "l"(src) : "memory")
#define CPA_COMMIT() asm volatile("cp.async.commit_group;" ::: "memory")
#define CPA_WAIT0()  asm volatile("cp.async.wait_group 0;" ::: "memory")

// ---------------------------------------------------------------------------
// Prep: fold BN into conv weights (single fp16), emit mma.sync B-fragments
// in final lane/register layout; fold bias; detect index dtype.
// ---------------------------------------------------------------------------
__global__ void prep_kernel(const float* __restrict__ conv_w,
                            const float* __restrict__ bg,
                            const float* __restrict__ bb,
                            const float* __restrict__ bm,
                            const float* __restrict__ bv,
                            const void*  __restrict__ pa1)
{
    int idx = blockIdx.x * blockDim.x + threadIdx.x;

    if (idx == 0) {
        const int* p = (const int*)pa1;   // int64 perm -> zero high words
        g_idx64 = (p[1] == 0 && p[3] == 0 && p[5] == 0 && p[7] == 0) ? 1 : 0;
    }
    if (idx < 384) {                      // bias fold [bk][L][o]
        int o = idx & 63, L = (idx >> 6) % 3, bk = idx / 192;
        float sc = bg[idx] * rsqrtf(bv[idx] + EPS_);
        g_bias[bk][L * 64 + o] = bb[idx] - bm[idx] * sc;
    }
    if (idx < 36864) {
        int q = idx;
        int reg  = q & 1;  q >>= 1;
        int lane = q & 31; q >>= 5;
        int kb   = q & 3;  q >>= 2;
        int nb   = q & 7;  q >>= 3;
        int t    = q % 3;  q /= 3;
        int L    = q % 3;
        int bk   = q / 3;

        int n  = nb * 8 + (lane >> 2);                 // output channel
        int k0 = kb * 16 + reg * 8 + (lane & 3) * 2;   // input channel pair
        int bni = (bk * 3 + L) * 64 + n;
        float sc = bg[bni] * rsqrtf(bv[bni] + EPS_);

        float w0 = conv_w[(((size_t)(bk * 3 + L) * 64 + n) * 64 + (k0 + 0)) * 3 + t] * sc;
        float w1 = conv_w[(((size_t)(bk * 3 + L) * 64 + n) * 64 + (k0 + 1)) * 3 + t] * sc;
        __half2 h = __floats2half2_rn(w0, w1);
        g_wfrag[idx] = *(uint32_t*)&h;
    }
}

// ---------------------------------------------------------------------------
// Fused block: gather -> 3 x (mma.sync conv + BN + act) -> residual -> scatter
// One CTA = 250 output points (256-row buffer), 256 threads, 8 warps x M=32.
// fp16 2-pass: D = x_hi*W + x_lo*W, weights single fp16 (B frags reused).
// ---------------------------------------------------------------------------
__global__ void __launch_bounds__(256, 1)
mc_block_kernel(const float* __restrict__ xin,
                const void*  __restrict__ pav,
                float* __restrict__ out,
                int bk)
{
    extern __shared__ uint8_t smem[];
    const uint32_t sbase = smem_u32(smem);
    const int tid = threadIdx.x, wid = tid >> 5, lane = tid & 31;
    const int b = blockIdx.y;
    const int ts = blockIdx.x * T_;
    const bool is64 = (g_idx64 != 0);
    const int*       pa32 = (const int*)pav;
    const long long* pa64 = (const long long*)pav;

    if (tid < 192) ((float*)(smem + SM_BIAS))[tid] = g_bias[bk][tid];

    // ---- stage layer-0 weight fragments (24KB) via cp.async (overlaps gather) ----
    {
        const uint8_t* src = (const uint8_t*)g_wfrag + (size_t)(bk * 3) * WBYTES;
        #pragma unroll
        for (int i = 0; i < 6; ++i) {
            int e = tid + i * 256;
            CPA16(sbase + SM_W + e * 16, src + (size_t)e * 16);
        }
        CPA_COMMIT();
    }

    // ---- gather 256 rows (points ts-3 .. ts+252) into pair0, fp16 hi/lo ----
    {
        const int r = tid;                 // one thread per row
        int gp = ts - 3 + r;
        bool ok = (gp >= 0) && (gp < N_);
        const float4* src = nullptr;
        if (ok) {
            long long prow = is64 ? pa64[(size_t)b * N_ + gp]
                                  : (long long)pa32[(size_t)b * N_ + gp];
            src = (const float4*)(xin + ((size_t)b * N_ + (size_t)prow) * 64);
        }
        uint8_t* bh0 = smem + SM_BUF;              // pair0 hi
        uint8_t* bl0 = bh0 + BUFBYTES;             // pair0 lo
        #pragma unroll
        for (int i = 0; i < 16; ++i) {
            float4 v = ok ? src[i] : make_float4(0.f, 0.f, 0.f, 0.f);
            uint2 p01 = pack2h(v.x, v.y);
            uint2 p23 = pack2h(v.z, v.w);
            uint32_t off = (uint32_t)(r * ROWSTRIDE + i * 8);
            *(uint2*)(bh0 + off) = make_uint2(p01.x, p23.x);
            *(uint2*)(bl0 + off) = make_uint2(p01.y, p23.y);
        }
    }

    CPA_WAIT0();
    __syncthreads();

    // A-operand ldmatrix row offsets: [slab][tap], rows clamped to [0,255]
    uint32_t aoff[2][3];
    #pragma unroll
    for (int s2 = 0; s2 < 2; ++s2)
        #pragma unroll
        for (int t = 0; t < 3; ++t) {
            int rr = wid * 32 + s2 * 16 + t - 1 + (lane & 15);
            rr = rr < 0 ? 0 : (rr > 255 ? 255 : rr);
            aoff[s2][t] = (uint32_t)(rr * ROWSTRIDE) + ((lane >> 4) * 16);
        }

    #pragma unroll
    for (int L = 0; L < 3; ++L) {
        const int inp = (L == 1) ? 1 : 0;          // L0:p0, L1:p1, L2:p0
        const uint32_t inHi = sbase + SM_BUF + (uint32_t)(inp * 2) * BUFBYTES;
        const uint32_t inLo = inHi + BUFBYTES;
        const uint8_t* wl = smem + SM_W + lane * 8;

        float d[2][8][4];
        #pragma unroll
        for (int s2 = 0; s2 < 2; ++s2)
            #pragma unroll
            for (int nb = 0; nb < 8; ++nb)
                #pragma unroll
                for (int j = 0; j < 4; ++j) d[s2][nb][j] = 0.f;

        #pragma unroll
        for (int t = 0; t < 3; ++t) {
            #pragma unroll
            for (int kb = 0; kb < 4; ++kb) {
                uint32_t a0[4], a1[4];
                LDSM4(a0, inHi + aoff[0][t] + kb * 32);
                LDSM4(a1, inHi + aoff[1][t] + kb * 32);

                uint2 bh[8];
                #pragma unroll
                for (int nb = 0; nb < 8; ++nb) {       // x_hi * W
                    bh[nb] = *(const uint2*)(wl + (size_t)(((t * 8 + nb) * 4 + kb) * 256));
                    mma_f16(d[0][nb], a0, bh[nb].x, bh[nb].y);
                    mma_f16(d[1][nb], a1, bh[nb].x, bh[nb].y);
                }
                LDSM4(a0, inLo + aoff[0][t] + kb * 32);
                LDSM4(a1, inLo + aoff[1][t] + kb * 32);
                #pragma unroll
                for (int nb = 0; nb < 8; ++nb) {       // x_lo * W (B regs reused)
                    mma_f16(d[0][nb], a0, bh[nb].x, bh[nb].y);
                    mma_f16(d[1][nb], a1, bh[nb].x, bh[nb].y);
                }
            }
        }

        // ---- epilogue ----
        const float* bias = (const float*)(smem + SM_BIAS) + L * 64;

        if (L < 2) {
            const int outp = (L == 0) ? 1 : 0;
            uint8_t* oh = smem + SM_BUF + (uint32_t)(outp * 2) * BUFBYTES;
            uint8_t* ol = oh + BUFBYTES;
            #pragma unroll
            for (int s2 = 0; s2 < 2; ++s2) {
                #pragma unroll
                for (int rh = 0; rh < 2; ++rh) {
                    const int r = wid * 32 + s2 * 16 + rh * 8 + (lane >> 2);
                    const int gp = ts - 3 + r;
                    const bool valid = (r >= L + 1) && (r <= 254 - L) && (gp >= 0) && (gp < N_);
                    #pragma unroll
                    for (int nb = 0; nb < 8; ++nb) {
                        const int c0 = nb * 8 + (lane & 3) * 2;
                        float v0 = valid ? fmaxf(d[s2][nb][rh * 2 + 0] + bias[c0], 0.f) : 0.f;
                        float v1 = valid ? fmaxf(d[s2][nb][rh * 2 + 1] + bias[c0 + 1], 0.f) : 0.f;
                        uint2 p = pack2h(v0, v1);
                        uint32_t off = (uint32_t)(r * ROWSTRIDE + c0 * 2);
                        *(uint32_t*)(oh + off) = p.x;
                        *(uint32_t*)(ol + off) = p.y;
                    }
                }
            }
            __syncthreads();     // epi visible + W buffer free
            {                    // stage next layer's weights (24KB)
                const uint8_t* src = (const uint8_t*)g_wfrag + (size_t)(bk * 3 + L + 1) * WBYTES;
                #pragma unroll
                for (int i = 0; i < 6; ++i) {
                    int e = tid + i * 256;
                    CPA16(sbase + SM_W + e * 16, src + (size_t)e * 16);
                }
                CPA_COMMIT();
                CPA_WAIT0();
            }
            __syncthreads();
        } else {
            // residual (re-gathered from gmem) + ReLU + permuted scatter
            #pragma unroll
            for (int s2 = 0; s2 < 2; ++s2) {
                #pragma unroll
                for (int rh = 0; rh < 2; ++rh) {
                    const int r = wid * 32 + s2 * 16 + rh * 8 + (lane >> 2);
                    const int gp = ts - 3 + r;
                    if (r >= 3 && r <= 252 && gp < N_) {
                        long long prow = is64 ? pa64[(size_t)b * N_ + gp]
                                              : (long long)pa32[(size_t)b * N_ + gp];
                        const float* xp = xin + ((size_t)b * N_ + (size_t)prow) * 64;
                        float* op = out + ((size_t)b * N_ + (size_t)prow) * 64;
                        #pragma unroll
                        for (int nb = 0; nb < 8; ++nb) {
                            const int c0 = nb * 8 + (lane & 3) * 2;
                            float2 xv = *(const float2*)(xp + c0);
                            float2 o2;
                            o2.x = fmaxf(xv.x + d[s2][nb][rh * 2 + 0] + bias[c0], 0.f);
                            o2.y = fmaxf(xv.y + d[s2][nb][rh * 2 + 1] + bias[c0 + 1], 0.f);
                            *(float2*)(op + c0) = o2;
                        }
                    }
                }
            }
        }
    }
}

// ---------------------------------------------------------------------------
extern "C" void kernel_launch(void* const* d_in, const int* in_sizes, int n_in,
                              void* d_out, int out_size)
{
    const float* x      = (const float*)d_in[0];
    const void*  pa1    = d_in[1];
    // d_in[2] = idx_re_1 (unused: re ∘ pa = id, scatter uses pa)
    const void*  pa2    = d_in[3];
    // d_in[4] = idx_re_2 (unused)
    const float* conv_w = (const float*)d_in[5];
    const float* bg     = (const float*)d_in[6];
    const float* bb     = (const float*)d_in[7];
    const float* bm     = (const float*)d_in[8];
    const float* bv     = (const float*)d_in[9];
    float* out = (float*)d_out;

    cudaFuncSetAttribute(mc_block_kernel,
                         cudaFuncAttributeMaxDynamicSharedMemorySize, SM_TOTAL);

    void* tmpp = nullptr;
    cudaGetSymbolAddress(&tmpp, g_tmp);

    prep_kernel<<<(36864 + 255) / 256, 256>>>(conv_w, bg, bb, bm, bv, pa1);

    dim3 grid(NTILE, B_);
    mc_block_kernel<<<grid, 256, SM_TOTAL>>>(x, pa1, (float*)tmpp, 0);
    mc_block_kernel<<<grid, 256, SM_TOTAL>>>((const float*)tmpp, pa2, out, 1);
}

// round 9
// speedup vs baseline: 3.0184x; 1.3432x over previous
#include <cuda_runtime.h>
#include <cuda_fp16.h>
#include <cstdint>

// ---------------- problem constants ----------------
#define B_    2
#define N_    262144
#define T_    250                     // valid output points per CTA
#define ROWS_ 256                     // buffer rows (halo 3 each side)
#define NTILE ((N_ + T_ - 1) / T_)    // 1049
#define EPS_  1e-5f

// ---------------- smem layout (bytes) ----------------
// 2 activation buffers (ping-pong, single fp16) of 256 rows x 144B
// 1 weight-fragment buffer 24KB (single fp16 weights, re-staged per layer)
// bias: 3 x 64 floats.  Total ~99KB -> ~129KB L1D survives.
#define ROWSTRIDE 144
#define BUFBYTES  (ROWS_ * ROWSTRIDE)      // 36864
#define SM_BUF    0
#define WBYTES    24576                    // 3 taps x 8 nb x 4 kb x 32 lanes x 8B
#define SM_W      (2 * BUFBYTES)           // 73728
#define SM_BIAS   (SM_W + WBYTES)          // 98304
#define SM_TOTAL  (SM_BIAS + 1024)         // 99328

// ---------------- device globals (no allocs allowed) ----------------
__device__ float   g_tmp[(size_t)B_ * N_ * 64];     // inter-block scratch (128 MB)
__device__ __align__(16) uint32_t g_wfrag[36864];   // [bk][L][t][nb][kb][lane][reg] fp16x2
__device__ float   g_bias[2][192];                  // folded bias [blk][L*64+o]
__device__ int     g_idx64;

// ---------------- helpers ----------------
__device__ __forceinline__ uint32_t smem_u32(const void* p) {
    uint32_t a;
    asm("{ .reg .u64 t; cvta.to.shared.u64 t, %1; cvt.u32.u64 %0, t; }" : "=r"(a) : "l"(p));
    return a;
}
__device__ __forceinline__ uint32_t packh(float v0, float v1) {
    __half2 h = __floats2half2_rn(v0, v1);
    return *(uint32_t*)&h;
}

__device__ __forceinline__ void mma_f16(float d[4], const uint32_t a[4],
                                        uint32_t b0, uint32_t b1) {
    asm volatile(
        "mma.sync.aligned.m16n8k16.row.col.f32.f16.f16.f32 "
        "{%0,%1,%2,%3}, {%4,%5,%6,%7}, {%8,%9}, {%0,%1,%2,%3};"
        : "+f"(d[0]), "+f"(d[1]), "+f"(d[2]), "+f"(d[3])
        : "r"(a[0]), "r"(a[1]), "r"(a[2]), "r"(a[3]), "r"(b0), "r"(b1));
}

#define LDSM4(a, addr)                                                         \
    asm volatile("ldmatrix.sync.aligned.m8n8.x4.shared.b16 {%0,%1,%2,%3}, [%4];" \
        : "=r"((a)[0]), "=r"((a)[1]), "=r"((a)[2]), "=r"((a)[3]) : "r"(addr))

#define CPA16(dst, src)                                                        \
    asm volatile("cp.async.cg.shared.global [%0], [%1], 16;"                   \
        :: "r"(dst), "l"(src) : "memory")
#define CPA_COMMIT() asm volatile("cp.async.commit_group;" ::: "memory")
#define CPA_WAIT0()  asm volatile("cp.async.wait_group 0;" ::: "memory")

// ---------------------------------------------------------------------------
// Prep: fold BN into conv weights (single fp16), emit mma.sync B-fragments
// in final lane/register layout; fold bias; detect index dtype.
// ---------------------------------------------------------------------------
__global__ void prep_kernel(const float* __restrict__ conv_w,
                            const float* __restrict__ bg,
                            const float* __restrict__ bb,
                            const float* __restrict__ bm,
                            const float* __restrict__ bv,
                            const void*  __restrict__ pa1)
{
    int idx = blockIdx.x * blockDim.x + threadIdx.x;

    if (idx == 0) {
        const int* p = (const int*)pa1;   // int64 perm -> zero high words
        g_idx64 = (p[1] == 0 && p[3] == 0 && p[5] == 0 && p[7] == 0) ? 1 : 0;
    }
    if (idx < 384) {                      // bias fold [bk][L][o]
        int o = idx & 63, L = (idx >> 6) % 3, bk = idx / 192;
        float sc = bg[idx] * rsqrtf(bv[idx] + EPS_);
        g_bias[bk][L * 64 + o] = bb[idx] - bm[idx] * sc;
    }
    if (idx < 36864) {
        int q = idx;
        int reg  = q & 1;  q >>= 1;
        int lane = q & 31; q >>= 5;
        int kb   = q & 3;  q >>= 2;
        int nb   = q & 7;  q >>= 3;
        int t    = q % 3;  q /= 3;
        int L    = q % 3;
        int bk   = q / 3;

        int n  = nb * 8 + (lane >> 2);                 // output channel
        int k0 = kb * 16 + reg * 8 + (lane & 3) * 2;   // input channel pair
        int bni = (bk * 3 + L) * 64 + n;
        float sc = bg[bni] * rsqrtf(bv[bni] + EPS_);

        float w0 = conv_w[(((size_t)(bk * 3 + L) * 64 + n) * 64 + (k0 + 0)) * 3 + t] * sc;
        float w1 = conv_w[(((size_t)(bk * 3 + L) * 64 + n) * 64 + (k0 + 1)) * 3 + t] * sc;
        g_wfrag[idx] = packh(w0, w1);
    }
}

// ---------------------------------------------------------------------------
// Fused block: gather -> 3 x (mma.sync conv + BN + act) -> residual -> scatter
// One CTA = 250 output points (256-row buffer), 256 threads, 8 warps x M=32.
// Single-pass fp16: activations and weights both fp16, fp32 accumulate.
// ---------------------------------------------------------------------------
__global__ void __launch_bounds__(256, 1)
mc_block_kernel(const float* __restrict__ xin,
                const void*  __restrict__ pav,
                float* __restrict__ out,
                int bk)
{
    extern __shared__ uint8_t smem[];
    const uint32_t sbase = smem_u32(smem);
    const int tid = threadIdx.x, wid = tid >> 5, lane = tid & 31;
    const int b = blockIdx.y;
    const int ts = blockIdx.x * T_;
    const bool is64 = (g_idx64 != 0);
    const int*       pa32 = (const int*)pav;
    const long long* pa64 = (const long long*)pav;

    if (tid < 192) ((float*)(smem + SM_BIAS))[tid] = g_bias[bk][tid];

    // ---- stage layer-0 weight fragments (24KB) via cp.async (overlaps gather) ----
    {
        const uint8_t* src = (const uint8_t*)g_wfrag + (size_t)(bk * 3) * WBYTES;
        #pragma unroll
        for (int i = 0; i < 6; ++i) {
            int e = tid + i * 256;
            CPA16(sbase + SM_W + e * 16, src + (size_t)e * 16);
        }
        CPA_COMMIT();
    }

    // ---- gather 256 rows (points ts-3 .. ts+252) into buf0, fp16 ----
    {
        const int r = tid;                 // one thread per row
        int gp = ts - 3 + r;
        bool ok = (gp >= 0) && (gp < N_);
        const float4* src = nullptr;
        if (ok) {
            long long prow = is64 ? pa64[(size_t)b * N_ + gp]
                                  : (long long)pa32[(size_t)b * N_ + gp];
            src = (const float4*)(xin + ((size_t)b * N_ + (size_t)prow) * 64);
        }
        uint8_t* b0 = smem + SM_BUF;
        #pragma unroll
        for (int i = 0; i < 16; ++i) {
            float4 v = ok ? src[i] : make_float4(0.f, 0.f, 0.f, 0.f);
            uint32_t off = (uint32_t)(r * ROWSTRIDE + i * 8);
            *(uint2*)(b0 + off) = make_uint2(packh(v.x, v.y), packh(v.z, v.w));
        }
    }

    CPA_WAIT0();
    __syncthreads();

    // A-operand ldmatrix row offsets: [slab][tap], rows clamped to [0,255]
    uint32_t aoff[2][3];
    #pragma unroll
    for (int s2 = 0; s2 < 2; ++s2)
        #pragma unroll
        for (int t = 0; t < 3; ++t) {
            int rr = wid * 32 + s2 * 16 + t - 1 + (lane & 15);
            rr = rr < 0 ? 0 : (rr > 255 ? 255 : rr);
            aoff[s2][t] = (uint32_t)(rr * ROWSTRIDE) + ((lane >> 4) * 16);
        }

    #pragma unroll
    for (int L = 0; L < 3; ++L) {
        const int inp = (L == 1) ? 1 : 0;          // L0:b0, L1:b1, L2:b0
        const uint32_t inB = sbase + SM_BUF + (uint32_t)inp * BUFBYTES;
        const uint8_t* wl = smem + SM_W + lane * 8;

        float d[2][8][4];
        #pragma unroll
        for (int s2 = 0; s2 < 2; ++s2)
            #pragma unroll
            for (int nb = 0; nb < 8; ++nb)
                #pragma unroll
                for (int j = 0; j < 4; ++j) d[s2][nb][j] = 0.f;

        #pragma unroll
        for (int t = 0; t < 3; ++t) {
            #pragma unroll
            for (int kb = 0; kb < 4; ++kb) {
                uint32_t a0[4], a1[4];
                LDSM4(a0, inB + aoff[0][t] + kb * 32);
                LDSM4(a1, inB + aoff[1][t] + kb * 32);

                #pragma unroll
                for (int nb = 0; nb < 8; ++nb) {
                    uint2 bh = *(const uint2*)(wl + (size_t)(((t * 8 + nb) * 4 + kb) * 256));
                    mma_f16(d[0][nb], a0, bh.x, bh.y);
                    mma_f16(d[1][nb], a1, bh.x, bh.y);
                }
            }
        }

        // ---- epilogue ----
        const float* bias = (const float*)(smem + SM_BIAS) + L * 64;

        if (L < 2) {
            const int outp = (L == 0) ? 1 : 0;
            uint8_t* ob = smem + SM_BUF + (uint32_t)outp * BUFBYTES;
            #pragma unroll
            for (int s2 = 0; s2 < 2; ++s2) {
                #pragma unroll
                for (int rh = 0; rh < 2; ++rh) {
                    const int r = wid * 32 + s2 * 16 + rh * 8 + (lane >> 2);
                    const int gp = ts - 3 + r;
                    const bool valid = (r >= L + 1) && (r <= 254 - L) && (gp >= 0) && (gp < N_);
                    #pragma unroll
                    for (int nb = 0; nb < 8; ++nb) {
                        const int c0 = nb * 8 + (lane & 3) * 2;
                        float v0 = valid ? fmaxf(d[s2][nb][rh * 2 + 0] + bias[c0], 0.f) : 0.f;
                        float v1 = valid ? fmaxf(d[s2][nb][rh * 2 + 1] + bias[c0 + 1], 0.f) : 0.f;
                        *(uint32_t*)(ob + (uint32_t)(r * ROWSTRIDE + c0 * 2)) = packh(v0, v1);
                    }
                }
            }
            __syncthreads();     // epi visible + W buffer free
            {                    // stage next layer's weights (24KB)
                const uint8_t* src = (const uint8_t*)g_wfrag + (size_t)(bk * 3 + L + 1) * WBYTES;
                #pragma unroll
                for (int i = 0; i < 6; ++i) {
                    int e = tid + i * 256;
                    CPA16(sbase + SM_W + e * 16, src + (size_t)e * 16);
                }
                CPA_COMMIT();
                CPA_WAIT0();
            }
            __syncthreads();
        } else {
            // residual (re-gathered from gmem) + ReLU + permuted scatter
            #pragma unroll
            for (int s2 = 0; s2 < 2; ++s2) {
                #pragma unroll
                for (int rh = 0; rh < 2; ++rh) {
                    const int r = wid * 32 + s2 * 16 + rh * 8 + (lane >> 2);
                    const int gp = ts - 3 + r;
                    if (r >= 3 && r <= 252 && gp < N_) {
                        long long prow = is64 ? pa64[(size_t)b * N_ + gp]
                                              : (long long)pa32[(size_t)b * N_ + gp];
                        const float* xp = xin + ((size_t)b * N_ + (size_t)prow) * 64;
                        float* op = out + ((size_t)b * N_ + (size_t)prow) * 64;
                        #pragma unroll
                        for (int nb = 0; nb < 8; ++nb) {
                            const int c0 = nb * 8 + (lane & 3) * 2;
                            float2 xv = *(const float2*)(xp + c0);
                            float2 o2;
                            o2.x = fmaxf(xv.x + d[s2][nb][rh * 2 + 0] + bias[c0], 0.f);
                            o2.y = fmaxf(xv.y + d[s2][nb][rh * 2 + 1] + bias[c0 + 1], 0.f);
                            *(float2*)(op + c0) = o2;
                        }
                    }
                }
            }
        }
    }
}

// ---------------------------------------------------------------------------
extern "C" void kernel_launch(void* const* d_in, const int* in_sizes, int n_in,
                              void* d_out, int out_size)
{
    const float* x      = (const float*)d_in[0];
    const void*  pa1    = d_in[1];
    // d_in[2] = idx_re_1 (unused: re ∘ pa = id, scatter uses pa)
    const void*  pa2    = d_in[3];
    // d_in[4] = idx_re_2 (unused)
    const float* conv_w = (const float*)d_in[5];
    const float* bg     = (const float*)d_in[6];
    const float* bb     = (const float*)d_in[7];
    const float* bm     = (const float*)d_in[8];
    const float* bv     = (const float*)d_in[9];
    float* out = (float*)d_out;

    cudaFuncSetAttribute(mc_block_kernel,
                         cudaFuncAttributeMaxDynamicSharedMemorySize, SM_TOTAL);

    void* tmpp = nullptr;
    cudaGetSymbolAddress(&tmpp, g_tmp);

    prep_kernel<<<(36864 + 255) / 256, 256>>>(conv_w, bg, bb, bm, bv, pa1);

    dim3 grid(NTILE, B_);
    mc_block_kernel<<<grid, 256, SM_TOTAL>>>(x, pa1, (float*)tmpp, 0);
    mc_block_kernel<<<grid, 256, SM_TOTAL>>>((const float*)tmpp, pa2, out, 1);
}

// round 10
// speedup vs baseline: 3.7561x; 1.2444x over previous
#include <cuda_runtime.h>
#include <cuda_fp16.h>
#include <cstdint>

// ---------------- problem constants ----------------
#define B_    2
#define N_    262144
#define T_    250                     // valid output points per CTA
#define ROWS_ 256                     // buffer rows (halo 3 each side)
#define NTILE ((N_ + T_ - 1) / T_)    // 1049
#define EPS_  1e-5f

// ---------------- smem layout (bytes) ----------------
// 2 activation buffers (ping-pong, single fp16) of 256 rows x 144B
// 1 weight-fragment buffer 24KB (single fp16 weights, re-staged per layer)
// bias: 3 x 64 floats.  Total ~99KB -> 2 CTAs/SM (198.7KB), ~30KB L1D left.
#define ROWSTRIDE 144
#define BUFBYTES  (ROWS_ * ROWSTRIDE)      // 36864
#define SM_BUF    0
#define WBYTES    24576                    // 3 taps x 8 nb x 4 kb x 32 lanes x 8B
#define SM_W      (2 * BUFBYTES)           // 73728
#define SM_BIAS   (SM_W + WBYTES)          // 98304
#define SM_TOTAL  (SM_BIAS + 1024)         // 99328

// ---------------- device globals (no allocs allowed) ----------------
__device__ float   g_tmp[(size_t)B_ * N_ * 64];     // inter-block scratch (128 MB)
__device__ __align__(16) uint32_t g_wfrag[36864];   // [bk][L][t][nb][kb][lane][reg] fp16x2
__device__ float   g_bias[2][192];                  // folded bias [blk][L*64+o]
__device__ int     g_idx64;

// ---------------- helpers ----------------
__device__ __forceinline__ uint32_t smem_u32(const void* p) {
    uint32_t a;
    asm("{ .reg .u64 t; cvta.to.shared.u64 t, %1; cvt.u32.u64 %0, t; }" : "=r"(a) : "l"(p));
    return a;
}
__device__ __forceinline__ uint32_t packh(float v0, float v1) {
    __half2 h = __floats2half2_rn(v0, v1);
    return *(uint32_t*)&h;
}

__device__ __forceinline__ void mma_f16(float d[4], const uint32_t a[4],
                                        uint32_t b0, uint32_t b1) {
    asm volatile(
        "mma.sync.aligned.m16n8k16.row.col.f32.f16.f16.f32 "
        "{%0,%1,%2,%3}, {%4,%5,%6,%7}, {%8,%9}, {%0,%1,%2,%3};"
        : "+f"(d[0]), "+f"(d[1]), "+f"(d[2]), "+f"(d[3])
        : "r"(a[0]), "r"(a[1]), "r"(a[2]), "r"(a[3]), "r"(b0), "r"(b1));
}

#define LDSM4(a, addr)                                                         \
    asm volatile("ldmatrix.sync.aligned.m8n8.x4.shared.b16 {%0,%1,%2,%3}, [%4];" \
        : "=r"((a)[0]), "=r"((a)[1]), "=r"((a)[2]), "=r"((a)[3]) : "r"(addr))

#define CPA16(dst, src)                                                        \
    asm volatile("cp.async.cg.shared.global [%0], [%1], 16;"                   \
        :: "r"(dst), "l"(src) : "memory")
#define CPA_COMMIT() asm volatile("cp.async.commit_group;" ::: "memory")
#define CPA_WAIT0()  asm volatile("cp.async.wait_group 0;" ::: "memory")

// ---------------------------------------------------------------------------
// Prep: fold BN into conv weights (single fp16), emit mma.sync B-fragments
// in final lane/register layout; fold bias; detect index dtype.
// ---------------------------------------------------------------------------
__global__ void prep_kernel(const float* __restrict__ conv_w,
                            const float* __restrict__ bg,
                            const float* __restrict__ bb,
                            const float* __restrict__ bm,
                            const float* __restrict__ bv,
                            const void*  __restrict__ pa1)
{
    int idx = blockIdx.x * blockDim.x + threadIdx.x;

    if (idx == 0) {
        const int* p = (const int*)pa1;   // int64 perm -> zero high words
        g_idx64 = (p[1] == 0 && p[3] == 0 && p[5] == 0 && p[7] == 0) ? 1 : 0;
    }
    if (idx < 384) {                      // bias fold [bk][L][o]
        int o = idx & 63, L = (idx >> 6) % 3, bk = idx / 192;
        float sc = bg[idx] * rsqrtf(bv[idx] + EPS_);
        g_bias[bk][L * 64 + o] = bb[idx] - bm[idx] * sc;
    }
    if (idx < 36864) {
        int q = idx;
        int reg  = q & 1;  q >>= 1;
        int lane = q & 31; q >>= 5;
        int kb   = q & 3;  q >>= 2;
        int nb   = q & 7;  q >>= 3;
        int t    = q % 3;  q /= 3;
        int L    = q % 3;
        int bk   = q / 3;

        int n  = nb * 8 + (lane >> 2);                 // output channel
        int k0 = kb * 16 + reg * 8 + (lane & 3) * 2;   // input channel pair
        int bni = (bk * 3 + L) * 64 + n;
        float sc = bg[bni] * rsqrtf(bv[bni] + EPS_);

        float w0 = conv_w[(((size_t)(bk * 3 + L) * 64 + n) * 64 + (k0 + 0)) * 3 + t] * sc;
        float w1 = conv_w[(((size_t)(bk * 3 + L) * 64 + n) * 64 + (k0 + 1)) * 3 + t] * sc;
        g_wfrag[idx] = packh(w0, w1);
    }
}

// ---------------------------------------------------------------------------
// Fused block: gather -> 3 x (mma.sync conv + BN + act) -> residual -> scatter
// One CTA = 250 output points (256-row buffer), 256 threads, 8 warps x M=32.
// Single-pass fp16. TWO CTAs per SM: cross-CTA overlap hides serial phases.
// ---------------------------------------------------------------------------
__global__ void __launch_bounds__(256, 2)
mc_block_kernel(const float* __restrict__ xin,
                const void*  __restrict__ pav,
                float* __restrict__ out,
                int bk)
{
    extern __shared__ uint8_t smem[];
    const uint32_t sbase = smem_u32(smem);
    const int tid = threadIdx.x, wid = tid >> 5, lane = tid & 31;
    const int b = blockIdx.y;
    const int ts = blockIdx.x * T_;
    const bool is64 = (g_idx64 != 0);
    const int*       pa32 = (const int*)pav;
    const long long* pa64 = (const long long*)pav;

    if (tid < 192) ((float*)(smem + SM_BIAS))[tid] = g_bias[bk][tid];

    // ---- stage layer-0 weight fragments (24KB) via cp.async (overlaps gather) ----
    {
        const uint8_t* src = (const uint8_t*)g_wfrag + (size_t)(bk * 3) * WBYTES;
        #pragma unroll
        for (int i = 0; i < 6; ++i) {
            int e = tid + i * 256;
            CPA16(sbase + SM_W + e * 16, src + (size_t)e * 16);
        }
        CPA_COMMIT();
    }

    // ---- gather 256 rows (points ts-3 .. ts+252) into buf0, fp16 ----
    {
        const int r = tid;                 // one thread per row
        int gp = ts - 3 + r;
        bool ok = (gp >= 0) && (gp < N_);
        const float4* src = nullptr;
        if (ok) {
            long long prow = is64 ? pa64[(size_t)b * N_ + gp]
                                  : (long long)pa32[(size_t)b * N_ + gp];
            src = (const float4*)(xin + ((size_t)b * N_ + (size_t)prow) * 64);
        }
        uint8_t* b0 = smem + SM_BUF;
        #pragma unroll
        for (int i = 0; i < 16; ++i) {
            float4 v = ok ? src[i] : make_float4(0.f, 0.f, 0.f, 0.f);
            uint32_t off = (uint32_t)(r * ROWSTRIDE + i * 8);
            *(uint2*)(b0 + off) = make_uint2(packh(v.x, v.y), packh(v.z, v.w));
        }
    }

    CPA_WAIT0();
    __syncthreads();

    // A-operand ldmatrix row offsets: [slab][tap], rows clamped to [0,255]
    uint32_t aoff[2][3];
    #pragma unroll
    for (int s2 = 0; s2 < 2; ++s2)
        #pragma unroll
        for (int t = 0; t < 3; ++t) {
            int rr = wid * 32 + s2 * 16 + t - 1 + (lane & 15);
            rr = rr < 0 ? 0 : (rr > 255 ? 255 : rr);
            aoff[s2][t] = (uint32_t)(rr * ROWSTRIDE) + ((lane >> 4) * 16);
        }

    #pragma unroll
    for (int L = 0; L < 3; ++L) {
        const int inp = (L == 1) ? 1 : 0;          // L0:b0, L1:b1, L2:b0
        const uint32_t inB = sbase + SM_BUF + (uint32_t)inp * BUFBYTES;
        const uint8_t* wl = smem + SM_W + lane * 8;

        float d[2][8][4];
        #pragma unroll
        for (int s2 = 0; s2 < 2; ++s2)
            #pragma unroll
            for (int nb = 0; nb < 8; ++nb)
                #pragma unroll
                for (int j = 0; j < 4; ++j) d[s2][nb][j] = 0.f;

        #pragma unroll
        for (int t = 0; t < 3; ++t) {
            #pragma unroll
            for (int kb = 0; kb < 4; ++kb) {
                uint32_t a0[4], a1[4];
                LDSM4(a0, inB + aoff[0][t] + kb * 32);
                LDSM4(a1, inB + aoff[1][t] + kb * 32);

                #pragma unroll
                for (int nb = 0; nb < 8; ++nb) {
                    uint2 bh = *(const uint2*)(wl + (size_t)(((t * 8 + nb) * 4 + kb) * 256));
                    mma_f16(d[0][nb], a0, bh.x, bh.y);
                    mma_f16(d[1][nb], a1, bh.x, bh.y);
                }
            }
        }

        // ---- epilogue ----
        const float* bias = (const float*)(smem + SM_BIAS) + L * 64;

        if (L < 2) {
            const int outp = (L == 0) ? 1 : 0;
            uint8_t* ob = smem + SM_BUF + (uint32_t)outp * BUFBYTES;
            #pragma unroll
            for (int s2 = 0; s2 < 2; ++s2) {
                #pragma unroll
                for (int rh = 0; rh < 2; ++rh) {
                    const int r = wid * 32 + s2 * 16 + rh * 8 + (lane >> 2);
                    const int gp = ts - 3 + r;
                    const bool valid = (r >= L + 1) && (r <= 254 - L) && (gp >= 0) && (gp < N_);
                    #pragma unroll
                    for (int nb = 0; nb < 8; ++nb) {
                        const int c0 = nb * 8 + (lane & 3) * 2;
                        float v0 = valid ? fmaxf(d[s2][nb][rh * 2 + 0] + bias[c0], 0.f) : 0.f;
                        float v1 = valid ? fmaxf(d[s2][nb][rh * 2 + 1] + bias[c0 + 1], 0.f) : 0.f;
                        *(uint32_t*)(ob + (uint32_t)(r * ROWSTRIDE + c0 * 2)) = packh(v0, v1);
                    }
                }
            }
            __syncthreads();     // epi visible + W buffer free
            {                    // stage next layer's weights (24KB)
                const uint8_t* src = (const uint8_t*)g_wfrag + (size_t)(bk * 3 + L + 1) * WBYTES;
                #pragma unroll
                for (int i = 0; i < 6; ++i) {
                    int e = tid + i * 256;
                    CPA16(sbase + SM_W + e * 16, src + (size_t)e * 16);
                }
                CPA_COMMIT();
                CPA_WAIT0();
            }
            __syncthreads();
        } else {
            // residual (re-gathered from gmem) + ReLU + permuted scatter
            #pragma unroll
            for (int s2 = 0; s2 < 2; ++s2) {
                #pragma unroll
                for (int rh = 0; rh < 2; ++rh) {
                    const int r = wid * 32 + s2 * 16 + rh * 8 + (lane >> 2);
                    const int gp = ts - 3 + r;
                    if (r >= 3 && r <= 252 && gp < N_) {
                        long long prow = is64 ? pa64[(size_t)b * N_ + gp]
                                              : (long long)pa32[(size_t)b * N_ + gp];
                        const float* xp = xin + ((size_t)b * N_ + (size_t)prow) * 64;
                        float* op = out + ((size_t)b * N_ + (size_t)prow) * 64;
                        #pragma unroll
                        for (int nb = 0; nb < 8; ++nb) {
                            const int c0 = nb * 8 + (lane & 3) * 2;
                            float2 xv = *(const float2*)(xp + c0);
                            float2 o2;
                            o2.x = fmaxf(xv.x + d[s2][nb][rh * 2 + 0] + bias[c0], 0.f);
                            o2.y = fmaxf(xv.y + d[s2][nb][rh * 2 + 1] + bias[c0 + 1], 0.f);
                            *(float2*)(op + c0) = o2;
                        }
                    }
                }
            }
        }
    }
}

// ---------------------------------------------------------------------------
extern "C" void kernel_launch(void* const* d_in, const int* in_sizes, int n_in,
                              void* d_out, int out_size)
{
    const float* x      = (const float*)d_in[0];
    const void*  pa1    = d_in[1];
    // d_in[2] = idx_re_1 (unused: re ∘ pa = id, scatter uses pa)
    const void*  pa2    = d_in[3];
    // d_in[4] = idx_re_2 (unused)
    const float* conv_w = (const float*)d_in[5];
    const float* bg     = (const float*)d_in[6];
    const float* bb     = (const float*)d_in[7];
    const float* bm     = (const float*)d_in[8];
    const float* bv     = (const float*)d_in[9];
    float* out = (float*)d_out;

    cudaFuncSetAttribute(mc_block_kernel,
                         cudaFuncAttributeMaxDynamicSharedMemorySize, SM_TOTAL);

    void* tmpp = nullptr;
    cudaGetSymbolAddress(&tmpp, g_tmp);

    prep_kernel<<<(36864 + 255) / 256, 256>>>(conv_w, bg, bb, bm, bv, pa1);

    dim3 grid(NTILE, B_);
    mc_block_kernel<<<grid, 256, SM_TOTAL>>>(x, pa1, (float*)tmpp, 0);
    mc_block_kernel<<<grid, 256, SM_TOTAL>>>((const float*)tmpp, pa2, out, 1);
}

// round 11
// speedup vs baseline: 3.8927x; 1.0364x over previous
#include <cuda_runtime.h>
#include <cuda_fp16.h>
#include <cstdint>

// ---------------- problem constants ----------------
#define B_    2
#define N_    262144
#define T_    250                     // valid output points per CTA
#define ROWS_ 256                     // buffer rows (halo 3 each side)
#define NTILE ((N_ + T_ - 1) / T_)    // 1049
#define EPS_  1e-5f

// ---------------- smem layout (bytes) ----------------
// 2 activation buffers (ping-pong, single fp16) of 256 rows x 144B
// 1 weight-fragment buffer 24KB (single fp16 weights, re-staged per layer)
// bias: 3 x 64 floats.  Total ~99KB -> 2 CTAs/SM (198.7KB), ~30KB L1D left.
#define ROWSTRIDE 144
#define BUFBYTES  (ROWS_ * ROWSTRIDE)      // 36864
#define SM_BUF    0
#define WBYTES    24576                    // 3t x 8nb x 2kb2 x (32 lanes x 16B)
#define SM_W      (2 * BUFBYTES)           // 73728
#define SM_BIAS   (SM_W + WBYTES)          // 98304
#define SM_TOTAL  (SM_BIAS + 1024)         // 99328

// ---------------- device globals (no allocs allowed) ----------------
__device__ float   g_tmp[(size_t)B_ * N_ * 64];     // inter-block scratch (128 MB)
__device__ __align__(16) uint32_t g_wfrag[36864];   // [bk][L][t][nb][kb2][lane][kbl][reg]
__device__ float   g_bias[2][192];                  // folded bias [blk][L*64+o]
__device__ int     g_idx64;

// ---------------- helpers ----------------
__device__ __forceinline__ uint32_t smem_u32(const void* p) {
    uint32_t a;
    asm("{ .reg .u64 t; cvta.to.shared.u64 t, %1; cvt.u32.u64 %0, t; }" : "=r"(a) : "l"(p));
    return a;
}
__device__ __forceinline__ uint32_t packh(float v0, float v1) {
    __half2 h = __floats2half2_rn(v0, v1);
    return *(uint32_t*)&h;
}

__device__ __forceinline__ void mma_f16(float d[4], const uint32_t a[4],
                                        uint32_t b0, uint32_t b1) {
    asm volatile(
        "mma.sync.aligned.m16n8k16.row.col.f32.f16.f16.f32 "
        "{%0,%1,%2,%3}, {%4,%5,%6,%7}, {%8,%9}, {%0,%1,%2,%3};"
        : "+f"(d[0]), "+f"(d[1]), "+f"(d[2]), "+f"(d[3])
        : "r"(a[0]), "r"(a[1]), "r"(a[2]), "r"(a[3]), "r"(b0), "r"(b1));
}

#define LDSM4(a, addr)                                                         \
    asm volatile("ldmatrix.sync.aligned.m8n8.x4.shared.b16 {%0,%1,%2,%3}, [%4];" \
        : "=r"((a)[0]), "=r"((a)[1]), "=r"((a)[2]), "=r"((a)[3]) : "r"(addr))

#define LDS128(v, addr)                                                        \
    asm volatile("ld.shared.v4.u32 {%0,%1,%2,%3}, [%4];"                       \
        : "=r"((v).x), "=r"((v).y), "=r"((v).z), "=r"((v).w) : "r"(addr))

#define CPA16(dst, src)                                                        \
    asm volatile("cp.async.cg.shared.global [%0], [%1], 16;"                   \
        :: "r"(dst), "l"(src) : "memory")
#define CPA_COMMIT() asm volatile("cp.async.commit_group;" ::: "memory")
#define CPA_WAIT0()  asm volatile("cp.async.wait_group 0;" ::: "memory")

// ---------------------------------------------------------------------------
// Prep: fold BN into conv weights (single fp16), emit mma.sync B-fragments.
// NEW layout: within (bk,L): block per (t,nb,kb2) of 512B = lane*16B holding
// {kb=2*kb2 (8B: reg0,reg1), kb=2*kb2+1 (8B)} -> warp LDS.128 is sequential.
// ---------------------------------------------------------------------------
__global__ void prep_kernel(const float* __restrict__ conv_w,
                            const float* __restrict__ bg,
                            const float* __restrict__ bb,
                            const float* __restrict__ bm,
                            const float* __restrict__ bv,
                            const void*  __restrict__ pa1)
{
    int idx = blockIdx.x * blockDim.x + threadIdx.x;

    if (idx == 0) {
        const int* p = (const int*)pa1;   // int64 perm -> zero high words
        g_idx64 = (p[1] == 0 && p[3] == 0 && p[5] == 0 && p[7] == 0) ? 1 : 0;
    }
    if (idx < 384) {                      // bias fold [bk][L][o]
        int o = idx & 63, L = (idx >> 6) % 3, bk = idx / 192;
        float sc = bg[idx] * rsqrtf(bv[idx] + EPS_);
        g_bias[bk][L * 64 + o] = bb[idx] - bm[idx] * sc;
    }
    if (idx < 36864) {
        // decode per the NEW uint32 layout:
        // within-layer = ((t*8+nb)*2 + kb2)*128 + lane*4 + kbl*2 + reg
        int q = idx;
        int reg  = q & 1;  q >>= 1;
        int kbl  = q & 1;  q >>= 1;
        int lane = q & 31; q >>= 5;
        int kb2  = q & 1;  q >>= 1;
        int nb   = q & 7;  q >>= 3;
        int t    = q % 3;  q /= 3;
        int L    = q % 3;
        int bk   = q / 3;
        int kb   = kb2 * 2 + kbl;

        int n  = nb * 8 + (lane >> 2);                 // output channel
        int k0 = kb * 16 + reg * 8 + (lane & 3) * 2;   // input channel pair
        int bni = (bk * 3 + L) * 64 + n;
        float sc = bg[bni] * rsqrtf(bv[bni] + EPS_);

        float w0 = conv_w[(((size_t)(bk * 3 + L) * 64 + n) * 64 + (k0 + 0)) * 3 + t] * sc;
        float w1 = conv_w[(((size_t)(bk * 3 + L) * 64 + n) * 64 + (k0 + 1)) * 3 + t] * sc;
        g_wfrag[idx] = packh(w0, w1);
    }
}

// ---------------------------------------------------------------------------
// Fused block: gather -> 3 x (mma.sync conv + BN + act) -> residual -> scatter
// One CTA = 250 output points (256-row buffer), 256 threads, 8 warps x M=32.
// Single-pass fp16, 2 CTAs/SM. B fragments loaded via LDS.128 (2 kb at once).
// ---------------------------------------------------------------------------
__global__ void __launch_bounds__(256, 2)
mc_block_kernel(const float* __restrict__ xin,
                const void*  __restrict__ pav,
                float* __restrict__ out,
                int bk)
{
    extern __shared__ uint8_t smem[];
    const uint32_t sbase = smem_u32(smem);
    const int tid = threadIdx.x, wid = tid >> 5, lane = tid & 31;
    const int b = blockIdx.y;
    const int ts = blockIdx.x * T_;
    const bool is64 = (g_idx64 != 0);
    const int*       pa32 = (const int*)pav;
    const long long* pa64 = (const long long*)pav;

    if (tid < 192) ((float*)(smem + SM_BIAS))[tid] = g_bias[bk][tid];

    // ---- stage layer-0 weight fragments (24KB) via cp.async (overlaps gather) ----
    {
        const uint8_t* src = (const uint8_t*)g_wfrag + (size_t)(bk * 3) * WBYTES;
        #pragma unroll
        for (int i = 0; i < 6; ++i) {
            int e = tid + i * 256;
            CPA16(sbase + SM_W + e * 16, src + (size_t)e * 16);
        }
        CPA_COMMIT();
    }

    // ---- gather 256 rows (points ts-3 .. ts+252) into buf0, fp16 ----
    {
        const int r = tid;                 // one thread per row
        int gp = ts - 3 + r;
        bool ok = (gp >= 0) && (gp < N_);
        const float4* src = nullptr;
        if (ok) {
            long long prow = is64 ? pa64[(size_t)b * N_ + gp]
                                  : (long long)pa32[(size_t)b * N_ + gp];
            src = (const float4*)(xin + ((size_t)b * N_ + (size_t)prow) * 64);
        }
        uint8_t* b0 = smem + SM_BUF;
        #pragma unroll
        for (int i = 0; i < 16; ++i) {
            float4 v = ok ? src[i] : make_float4(0.f, 0.f, 0.f, 0.f);
            uint32_t off = (uint32_t)(r * ROWSTRIDE + i * 8);
            *(uint2*)(b0 + off) = make_uint2(packh(v.x, v.y), packh(v.z, v.w));
        }
    }

    CPA_WAIT0();
    __syncthreads();

    // A-operand ldmatrix row offsets: [slab][tap], rows clamped to [0,255]
    uint32_t aoff[2][3];
    #pragma unroll
    for (int s2 = 0; s2 < 2; ++s2)
        #pragma unroll
        for (int t = 0; t < 3; ++t) {
            int rr = wid * 32 + s2 * 16 + t - 1 + (lane & 15);
            rr = rr < 0 ? 0 : (rr > 255 ? 255 : rr);
            aoff[s2][t] = (uint32_t)(rr * ROWSTRIDE) + ((lane >> 4) * 16);
        }

    #pragma unroll
    for (int L = 0; L < 3; ++L) {
        const int inp = (L == 1) ? 1 : 0;          // L0:b0, L1:b1, L2:b0
        const uint32_t inB = sbase + SM_BUF + (uint32_t)inp * BUFBYTES;
        const uint32_t wl = sbase + SM_W + (uint32_t)lane * 16;

        float d[2][8][4];
        #pragma unroll
        for (int s2 = 0; s2 < 2; ++s2)
            #pragma unroll
            for (int nb = 0; nb < 8; ++nb)
                #pragma unroll
                for (int j = 0; j < 4; ++j) d[s2][nb][j] = 0.f;

        #pragma unroll
        for (int t = 0; t < 3; ++t) {
            #pragma unroll
            for (int kb2 = 0; kb2 < 2; ++kb2) {
                // A fragments for both kb of this pair, both slabs
                uint32_t a00[4], a10[4], a01[4], a11[4];
                LDSM4(a00, inB + aoff[0][t] + (kb2 * 2 + 0) * 32);
                LDSM4(a10, inB + aoff[1][t] + (kb2 * 2 + 0) * 32);
                LDSM4(a01, inB + aoff[0][t] + (kb2 * 2 + 1) * 32);
                LDSM4(a11, inB + aoff[1][t] + (kb2 * 2 + 1) * 32);

                #pragma unroll
                for (int nb = 0; nb < 8; ++nb) {
                    uint4 bq;                 // {kb even: x,y | kb odd: z,w}
                    LDS128(bq, wl + (uint32_t)(((t * 8 + nb) * 2 + kb2) * 512));
                    mma_f16(d[0][nb], a00, bq.x, bq.y);
                    mma_f16(d[1][nb], a10, bq.x, bq.y);
                    mma_f16(d[0][nb], a01, bq.z, bq.w);
                    mma_f16(d[1][nb], a11, bq.z, bq.w);
                }
            }
        }

        // ---- epilogue ----
        const float* bias = (const float*)(smem + SM_BIAS) + L * 64;

        if (L < 2) {
            const int outp = (L == 0) ? 1 : 0;
            uint8_t* ob = smem + SM_BUF + (uint32_t)outp * BUFBYTES;
            #pragma unroll
            for (int s2 = 0; s2 < 2; ++s2) {
                #pragma unroll
                for (int rh = 0; rh < 2; ++rh) {
                    const int r = wid * 32 + s2 * 16 + rh * 8 + (lane >> 2);
                    const int gp = ts - 3 + r;
                    const bool valid = (r >= L + 1) && (r <= 254 - L) && (gp >= 0) && (gp < N_);
                    #pragma unroll
                    for (int nb = 0; nb < 8; ++nb) {
                        const int c0 = nb * 8 + (lane & 3) * 2;
                        float v0 = valid ? fmaxf(d[s2][nb][rh * 2 + 0] + bias[c0], 0.f) : 0.f;
                        float v1 = valid ? fmaxf(d[s2][nb][rh * 2 + 1] + bias[c0 + 1], 0.f) : 0.f;
                        *(uint32_t*)(ob + (uint32_t)(r * ROWSTRIDE + c0 * 2)) = packh(v0, v1);
                    }
                }
            }
            __syncthreads();     // epi visible + W buffer free
            {                    // stage next layer's weights (24KB)
                const uint8_t* src = (const uint8_t*)g_wfrag + (size_t)(bk * 3 + L + 1) * WBYTES;
                #pragma unroll
                for (int i = 0; i < 6; ++i) {
                    int e = tid + i * 256;
                    CPA16(sbase + SM_W + e * 16, src + (size_t)e * 16);
                }
                CPA_COMMIT();
                CPA_WAIT0();
            }
            __syncthreads();
        } else {
            // residual (re-gathered from gmem) + ReLU + permuted scatter
            #pragma unroll
            for (int s2 = 0; s2 < 2; ++s2) {
                #pragma unroll
                for (int rh = 0; rh < 2; ++rh) {
                    const int r = wid * 32 + s2 * 16 + rh * 8 + (lane >> 2);
                    const int gp = ts - 3 + r;
                    if (r >= 3 && r <= 252 && gp < N_) {
                        long long prow = is64 ? pa64[(size_t)b * N_ + gp]
                                              : (long long)pa32[(size_t)b * N_ + gp];
                        const float* xp = xin + ((size_t)b * N_ + (size_t)prow) * 64;
                        float* op = out + ((size_t)b * N_ + (size_t)prow) * 64;
                        #pragma unroll
                        for (int nb = 0; nb < 8; ++nb) {
                            const int c0 = nb * 8 + (lane & 3) * 2;
                            float2 xv = *(const float2*)(xp + c0);
                            float2 o2;
                            o2.x = fmaxf(xv.x + d[s2][nb][rh * 2 + 0] + bias[c0], 0.f);
                            o2.y = fmaxf(xv.y + d[s2][nb][rh * 2 + 1] + bias[c0 + 1], 0.f);
                            *(float2*)(op + c0) = o2;
                        }
                    }
                }
            }
        }
    }
}

// ---------------------------------------------------------------------------
extern "C" void kernel_launch(void* const* d_in, const int* in_sizes, int n_in,
                              void* d_out, int out_size)
{
    const float* x      = (const float*)d_in[0];
    const void*  pa1    = d_in[1];
    // d_in[2] = idx_re_1 (unused: re ∘ pa = id, scatter uses pa)
    const void*  pa2    = d_in[3];
    // d_in[4] = idx_re_2 (unused)
    const float* conv_w = (const float*)d_in[5];
    const float* bg     = (const float*)d_in[6];
    const float* bb     = (const float*)d_in[7];
    const float* bm     = (const float*)d_in[8];
    const float* bv     = (const float*)d_in[9];
    float* out = (float*)d_out;

    cudaFuncSetAttribute(mc_block_kernel,
                         cudaFuncAttributeMaxDynamicSharedMemorySize, SM_TOTAL);

    void* tmpp = nullptr;
    cudaGetSymbolAddress(&tmpp, g_tmp);

    prep_kernel<<<(36864 + 255) / 256, 256>>>(conv_w, bg, bb, bm, bv, pa1);

    dim3 grid(NTILE, B_);
    mc_block_kernel<<<grid, 256, SM_TOTAL>>>(x, pa1, (float*)tmpp, 0);
    mc_block_kernel<<<grid, 256, SM_TOTAL>>>((const float*)tmpp, pa2, out, 1);
}

// round 12
// speedup vs baseline: 4.1482x; 1.0656x over previous
#include <cuda_runtime.h>
#include <cuda_fp16.h>
#include <cstdint>

// ---------------- problem constants ----------------
#define B_    2
#define N_    262144
#define T_    250                     // valid output points per CTA
#define ROWS_ 256                     // buffer rows (halo 3 each side)
#define NTILE ((N_ + T_ - 1) / T_)    // 1049
#define EPS_  1e-5f

// ---------------- smem layout (bytes) ----------------
// 2 activation buffers (ping-pong, single fp16) of 256 rows x 144B
// 1 weight-fragment buffer 24KB (single fp16 weights, re-staged per layer)
// bias: 3 x 64 floats.  Total ~99KB -> 2 CTAs/SM (198.7KB), ~30KB L1D left.
#define ROWSTRIDE 144
#define BUFBYTES  (ROWS_ * ROWSTRIDE)      // 36864
#define SM_BUF    0
#define WBYTES    24576                    // 3t x 8nb x 2kb2 x (32 lanes x 16B)
#define SM_W      (2 * BUFBYTES)           // 73728
#define SM_BIAS   (SM_W + WBYTES)          // 98304
#define SM_TOTAL  (SM_BIAS + 1024)         // 99328

// ---------------- device globals (no allocs allowed) ----------------
__device__ float   g_tmp[(size_t)B_ * N_ * 64];     // inter-block scratch (fp16 used)
__device__ __align__(16) uint32_t g_wfrag[36864];   // [bk][L][t][nb][kb2][lane][kbl][reg]
__device__ float   g_bias[2][192];                  // folded bias [blk][L*64+o]
__device__ int     g_idx64;

// ---------------- helpers ----------------
__device__ __forceinline__ uint32_t smem_u32(const void* p) {
    uint32_t a;
    asm("{ .reg .u64 t; cvta.to.shared.u64 t, %1; cvt.u32.u64 %0, t; }" : "=r"(a) : "l"(p));
    return a;
}
__device__ __forceinline__ uint32_t packh(float v0, float v1) {
    __half2 h = __floats2half2_rn(v0, v1);
    return *(uint32_t*)&h;
}

__device__ __forceinline__ void mma_f16(float d[4], const uint32_t a[4],
                                        uint32_t b0, uint32_t b1) {
    asm volatile(
        "mma.sync.aligned.m16n8k16.row.col.f32.f16.f16.f32 "
        "{%0,%1,%2,%3}, {%4,%5,%6,%7}, {%8,%9}, {%0,%1,%2,%3};"
        : "+f"(d[0]), "+f"(d[1]), "+f"(d[2]), "+f"(d[3])
        : "r"(a[0]), "r"(a[1]), "r"(a[2]), "r"(a[3]), "r"(b0), "r"(b1));
}

#define LDSM4(a, addr)                                                         \
    asm volatile("ldmatrix.sync.aligned.m8n8.x4.shared.b16 {%0,%1,%2,%3}, [%4];" \
        : "=r"((a)[0]), "=r"((a)[1]), "=r"((a)[2]), "=r"((a)[3]) : "r"(addr))

#define LDS128(v, addr)                                                        \
    asm volatile("ld.shared.v4.u32 {%0,%1,%2,%3}, [%4];"                       \
        : "=r"((v).x), "=r"((v).y), "=r"((v).z), "=r"((v).w) : "r"(addr))

#define CPA16(dst, src)                                                        \
    asm volatile("cp.async.cg.shared.global [%0], [%1], 16;"                   \
        :: "r"(dst), "l"(src) : "memory")
#define CPA_COMMIT() asm volatile("cp.async.commit_group;" ::: "memory")
#define CPA_WAIT0()  asm volatile("cp.async.wait_group 0;" ::: "memory")

// ---------------------------------------------------------------------------
// Prep: fold BN into conv weights (single fp16), emit mma.sync B-fragments.
// Layout: within (bk,L): block per (t,nb,kb2) of 512B = lane*16B holding
// {kb=2*kb2 (8B: reg0,reg1), kb=2*kb2+1 (8B)} -> warp LDS.128 is sequential.
// ---------------------------------------------------------------------------
__global__ void prep_kernel(const float* __restrict__ conv_w,
                            const float* __restrict__ bg,
                            const float* __restrict__ bb,
                            const float* __restrict__ bm,
                            const float* __restrict__ bv,
                            const void*  __restrict__ pa1)
{
    int idx = blockIdx.x * blockDim.x + threadIdx.x;

    if (idx == 0) {
        const int* p = (const int*)pa1;   // int64 perm -> zero high words
        g_idx64 = (p[1] == 0 && p[3] == 0 && p[5] == 0 && p[7] == 0) ? 1 : 0;
    }
    if (idx < 384) {                      // bias fold [bk][L][o]
        int o = idx & 63, L = (idx >> 6) % 3, bk = idx / 192;
        float sc = bg[idx] * rsqrtf(bv[idx] + EPS_);
        g_bias[bk][L * 64 + o] = bb[idx] - bm[idx] * sc;
    }
    if (idx < 36864) {
        int q = idx;
        int reg  = q & 1;  q >>= 1;
        int kbl  = q & 1;  q >>= 1;
        int lane = q & 31; q >>= 5;
        int kb2  = q & 1;  q >>= 1;
        int nb   = q & 7;  q >>= 3;
        int t    = q % 3;  q /= 3;
        int L    = q % 3;
        int bk   = q / 3;
        int kb   = kb2 * 2 + kbl;

        int n  = nb * 8 + (lane >> 2);                 // output channel
        int k0 = kb * 16 + reg * 8 + (lane & 3) * 2;   // input channel pair
        int bni = (bk * 3 + L) * 64 + n;
        float sc = bg[bni] * rsqrtf(bv[bni] + EPS_);

        float w0 = conv_w[(((size_t)(bk * 3 + L) * 64 + n) * 64 + (k0 + 0)) * 3 + t] * sc;
        float w1 = conv_w[(((size_t)(bk * 3 + L) * 64 + n) * 64 + (k0 + 1)) * 3 + t] * sc;
        g_wfrag[idx] = packh(w0, w1);
    }
}

// ---------------------------------------------------------------------------
// Fused block: gather -> 3 x (mma.sync conv + BN + act) -> residual -> scatter
// One CTA = 250 output points (256-row buffer), 256 threads, 8 warps x M=32.
// Single-pass fp16, 2 CTAs/SM. Templated on in/out dtype: the inter-block
// intermediate lives in fp16 (halves gather/scatter/residual DRAM traffic).
// ---------------------------------------------------------------------------
template<bool INF16, bool OUTF16>
__global__ void __launch_bounds__(256, 2)
mc_block_kernel(const void* __restrict__ xinv,
                const void*  __restrict__ pav,
                void* __restrict__ outv,
                int bk)
{
    extern __shared__ uint8_t smem[];
    const uint32_t sbase = smem_u32(smem);
    const int tid = threadIdx.x, wid = tid >> 5, lane = tid & 31;
    const int b = blockIdx.y;
    const int ts = blockIdx.x * T_;
    const bool is64 = (g_idx64 != 0);
    const int*       pa32 = (const int*)pav;
    const long long* pa64 = (const long long*)pav;
    const float*  xf = (const float*)xinv;
    const __half* xh = (const __half*)xinv;

    if (tid < 192) ((float*)(smem + SM_BIAS))[tid] = g_bias[bk][tid];

    // ---- stage layer-0 weight fragments (24KB) via cp.async (overlaps gather) ----
    {
        const uint8_t* src = (const uint8_t*)g_wfrag + (size_t)(bk * 3) * WBYTES;
        #pragma unroll
        for (int i = 0; i < 6; ++i) {
            int e = tid + i * 256;
            CPA16(sbase + SM_W + e * 16, src + (size_t)e * 16);
        }
        CPA_COMMIT();
    }

    // ---- gather 256 rows (points ts-3 .. ts+252) into buf0, fp16 ----
    {
        const int r = tid;                 // one thread per row
        int gp = ts - 3 + r;
        bool ok = (gp >= 0) && (gp < N_);
        long long prow = 0;
        if (ok) prow = is64 ? pa64[(size_t)b * N_ + gp]
                            : (long long)pa32[(size_t)b * N_ + gp];
        uint8_t* b0 = smem + SM_BUF;
        if (INF16) {
            const uint4* src = (const uint4*)(xh + ((size_t)b * N_ + (size_t)prow) * 64);
            #pragma unroll
            for (int i = 0; i < 8; ++i) {
                uint4 v = ok ? src[i] : make_uint4(0u, 0u, 0u, 0u);
                *(uint4*)(b0 + (uint32_t)(r * ROWSTRIDE + i * 16)) = v;
            }
        } else {
            const float4* src = (const float4*)(xf + ((size_t)b * N_ + (size_t)prow) * 64);
            #pragma unroll
            for (int i = 0; i < 16; ++i) {
                float4 v = ok ? src[i] : make_float4(0.f, 0.f, 0.f, 0.f);
                uint32_t off = (uint32_t)(r * ROWSTRIDE + i * 8);
                *(uint2*)(b0 + off) = make_uint2(packh(v.x, v.y), packh(v.z, v.w));
            }
        }
    }

    CPA_WAIT0();
    __syncthreads();

    // A-operand ldmatrix row offsets: [slab][tap], rows clamped to [0,255]
    uint32_t aoff[2][3];
    #pragma unroll
    for (int s2 = 0; s2 < 2; ++s2)
        #pragma unroll
        for (int t = 0; t < 3; ++t) {
            int rr = wid * 32 + s2 * 16 + t - 1 + (lane & 15);
            rr = rr < 0 ? 0 : (rr > 255 ? 255 : rr);
            aoff[s2][t] = (uint32_t)(rr * ROWSTRIDE) + ((lane >> 4) * 16);
        }

    #pragma unroll
    for (int L = 0; L < 3; ++L) {
        const int inp = (L == 1) ? 1 : 0;          // L0:b0, L1:b1, L2:b0
        const uint32_t inB = sbase + SM_BUF + (uint32_t)inp * BUFBYTES;
        const uint32_t wl = sbase + SM_W + (uint32_t)lane * 16;

        float d[2][8][4];
        #pragma unroll
        for (int s2 = 0; s2 < 2; ++s2)
            #pragma unroll
            for (int nb = 0; nb < 8; ++nb)
                #pragma unroll
                for (int j = 0; j < 4; ++j) d[s2][nb][j] = 0.f;

        #pragma unroll
        for (int t = 0; t < 3; ++t) {
            #pragma unroll
            for (int kb2 = 0; kb2 < 2; ++kb2) {
                uint32_t a00[4], a10[4], a01[4], a11[4];
                LDSM4(a00, inB + aoff[0][t] + (kb2 * 2 + 0) * 32);
                LDSM4(a10, inB + aoff[1][t] + (kb2 * 2 + 0) * 32);
                LDSM4(a01, inB + aoff[0][t] + (kb2 * 2 + 1) * 32);
                LDSM4(a11, inB + aoff[1][t] + (kb2 * 2 + 1) * 32);

                #pragma unroll
                for (int nb = 0; nb < 8; ++nb) {
                    uint4 bq;                 // {kb even: x,y | kb odd: z,w}
                    LDS128(bq, wl + (uint32_t)(((t * 8 + nb) * 2 + kb2) * 512));
                    mma_f16(d[0][nb], a00, bq.x, bq.y);
                    mma_f16(d[1][nb], a10, bq.x, bq.y);
                    mma_f16(d[0][nb], a01, bq.z, bq.w);
                    mma_f16(d[1][nb], a11, bq.z, bq.w);
                }
            }
        }

        // ---- epilogue ----
        const float* bias = (const float*)(smem + SM_BIAS) + L * 64;

        if (L < 2) {
            const int outp = (L == 0) ? 1 : 0;
            uint8_t* ob = smem + SM_BUF + (uint32_t)outp * BUFBYTES;
            #pragma unroll
            for (int s2 = 0; s2 < 2; ++s2) {
                #pragma unroll
                for (int rh = 0; rh < 2; ++rh) {
                    const int r = wid * 32 + s2 * 16 + rh * 8 + (lane >> 2);
                    const int gp = ts - 3 + r;
                    const bool valid = (r >= L + 1) && (r <= 254 - L) && (gp >= 0) && (gp < N_);
                    #pragma unroll
                    for (int nb = 0; nb < 8; ++nb) {
                        const int c0 = nb * 8 + (lane & 3) * 2;
                        float v0 = valid ? fmaxf(d[s2][nb][rh * 2 + 0] + bias[c0], 0.f) : 0.f;
                        float v1 = valid ? fmaxf(d[s2][nb][rh * 2 + 1] + bias[c0 + 1], 0.f) : 0.f;
                        *(uint32_t*)(ob + (uint32_t)(r * ROWSTRIDE + c0 * 2)) = packh(v0, v1);
                    }
                }
            }
            __syncthreads();     // epi visible + W buffer free
            {                    // stage next layer's weights (24KB)
                const uint8_t* src = (const uint8_t*)g_wfrag + (size_t)(bk * 3 + L + 1) * WBYTES;
                #pragma unroll
                for (int i = 0; i < 6; ++i) {
                    int e = tid + i * 256;
                    CPA16(sbase + SM_W + e * 16, src + (size_t)e * 16);
                }
                CPA_COMMIT();
                CPA_WAIT0();
            }
            __syncthreads();
        } else {
            // residual (re-gathered from gmem) + ReLU + permuted scatter
            #pragma unroll
            for (int s2 = 0; s2 < 2; ++s2) {
                #pragma unroll
                for (int rh = 0; rh < 2; ++rh) {
                    const int r = wid * 32 + s2 * 16 + rh * 8 + (lane >> 2);
                    const int gp = ts - 3 + r;
                    if (r >= 3 && r <= 252 && gp < N_) {
                        long long prow = is64 ? pa64[(size_t)b * N_ + gp]
                                              : (long long)pa32[(size_t)b * N_ + gp];
                        const size_t rowbase = ((size_t)b * N_ + (size_t)prow) * 64;
                        #pragma unroll
                        for (int nb = 0; nb < 8; ++nb) {
                            const int c0 = nb * 8 + (lane & 3) * 2;
                            float2 xv;
                            if (INF16) {
                                uint32_t u = *(const uint32_t*)(xh + rowbase + c0);
                                __half2 h2 = *(__half2*)&u;
                                xv.x = __low2float(h2); xv.y = __high2float(h2);
                            } else {
                                xv = *(const float2*)(xf + rowbase + c0);
                            }
                            float o0 = fmaxf(xv.x + d[s2][nb][rh * 2 + 0] + bias[c0], 0.f);
                            float o1 = fmaxf(xv.y + d[s2][nb][rh * 2 + 1] + bias[c0 + 1], 0.f);
                            if (OUTF16) {
                                *(uint32_t*)((__half*)outv + rowbase + c0) = packh(o0, o1);
                            } else {
                                *(float2*)((float*)outv + rowbase + c0) = make_float2(o0, o1);
                            }
                        }
                    }
                }
            }
        }
    }
}

// ---------------------------------------------------------------------------
extern "C" void kernel_launch(void* const* d_in, const int* in_sizes, int n_in,
                              void* d_out, int out_size)
{
    const float* x      = (const float*)d_in[0];
    const void*  pa1    = d_in[1];
    // d_in[2] = idx_re_1 (unused: re ∘ pa = id, scatter uses pa)
    const void*  pa2    = d_in[3];
    // d_in[4] = idx_re_2 (unused)
    const float* conv_w = (const float*)d_in[5];
    const float* bg     = (const float*)d_in[6];
    const float* bb     = (const float*)d_in[7];
    const float* bm     = (const float*)d_in[8];
    const float* bv     = (const float*)d_in[9];
    float* out = (float*)d_out;

    cudaFuncSetAttribute(mc_block_kernel<false, true>,
                         cudaFuncAttributeMaxDynamicSharedMemorySize, SM_TOTAL);
    cudaFuncSetAttribute(mc_block_kernel<true, false>,
                         cudaFuncAttributeMaxDynamicSharedMemorySize, SM_TOTAL);

    void* tmpp = nullptr;
    cudaGetSymbolAddress(&tmpp, g_tmp);

    prep_kernel<<<(36864 + 255) / 256, 256>>>(conv_w, bg, bb, bm, bv, pa1);

    dim3 grid(NTILE, B_);
    mc_block_kernel<false, true><<<grid, 256, SM_TOTAL>>>(x, pa1, tmpp, 0);
    mc_block_kernel<true, false><<<grid, 256, SM_TOTAL>>>(tmpp, pa2, out, 1);
}

// round 15
// speedup vs baseline: 4.4400x; 1.0704x over previous
#include <cuda_runtime.h>
#include <cuda_fp16.h>
#include <cstdint>

// ---------------- problem constants ----------------
#define B_    2
#define N_    262144
#define T_    250                     // valid output points per CTA
#define ROWS_ 256                     // buffer rows (halo 3 each side)
#define NTILE ((N_ + T_ - 1) / T_)    // 1049
#define EPS_  1e-5f

// ---------------- smem layout (bytes) ----------------
// b0 = gathered x (PRESERVED for residual), b1 = h1 then h2 (L1 in-place)
// 1 weight-fragment buffer 24KB (single fp16 weights, re-staged per layer)
// bias: 3 x 64 floats.  Total ~99KB -> 2 CTAs/SM (198.7KB), ~30KB L1D left.
#define ROWSTRIDE 144
#define BUFBYTES  (ROWS_ * ROWSTRIDE)      // 36864
#define SM_BUF    0
#define WBYTES    24576                    // 3t x 8nb x 2kb2 x (32 lanes x 16B)
#define SM_W      (2 * BUFBYTES)           // 73728
#define SM_BIAS   (SM_W + WBYTES)          // 98304
#define SM_TOTAL  (SM_BIAS + 1024)         // 99328

// ---------------- device globals (no allocs allowed) ----------------
__device__ float   g_tmp[(size_t)B_ * N_ * 64];     // inter-block scratch (fp16 used)
__device__ __align__(16) uint32_t g_wfrag[36864];   // [bk][L][t][nb][kb2][lane][kbl][reg]
__device__ float   g_bias[2][192];                  // folded bias [blk][L*64+o]
__device__ int     g_idx64;

// ---------------- helpers ----------------
__device__ __forceinline__ uint32_t smem_u32(const void* p) {
    uint32_t a;
    asm("{ .reg .u64 t; cvta.to.shared.u64 t, %1; cvt.u32.u64 %0, t; }" : "=r"(a) : "l"(p));
    return a;
}
__device__ __forceinline__ uint32_t packh(float v0, float v1) {
    __half2 h = __floats2half2_rn(v0, v1);
    return *(uint32_t*)&h;
}

__device__ __forceinline__ void mma_f16(float d[4], const uint32_t a[4],
                                        uint32_t b0, uint32_t b1) {
    asm volatile(
        "mma.sync.aligned.m16n8k16.row.col.f32.f16.f16.f32 "
        "{%0,%1,%2,%3}, {%4,%5,%6,%7}, {%8,%9}, {%0,%1,%2,%3};"
        : "+f"(d[0]), "+f"(d[1]), "+f"(d[2]), "+f"(d[3])
        : "r"(a[0]), "r"(a[1]), "r"(a[2]), "r"(a[3]), "r"(b0), "r"(b1));
}

#define LDSM4(a, addr)                                                         \
    asm volatile("ldmatrix.sync.aligned.m8n8.x4.shared.b16 {%0,%1,%2,%3}, [%4];" \
        : "=r"((a)[0]), "=r"((a)[1]), "=r"((a)[2]), "=r"((a)[3]) : "r"(addr))

#define LDS128(v, addr)                                                        \
    asm volatile("ld.shared.v4.u32 {%0,%1,%2,%3}, [%4];"                       \
        : "=r"((v).x), "=r"((v).y), "=r"((v).z), "=r"((v).w) : "r"(addr))

#define CPA16(dst, src)                                                        \
    asm volatile("cp.async.cg.shared.global [%0], [%1], 16;"                   \
        :: "r"(dst), "l"(src) : "memory")
#define CPA_COMMIT() asm volatile("cp.async.commit_group;" ::: "memory")
#define CPA_WAIT0()  asm volatile("cp.async.wait_group 0;" ::: "memory")

// ---------------------------------------------------------------------------
// Prep: fold BN into conv weights (single fp16), emit mma.sync B-fragments.
// Layout: within (bk,L): block per (t,nb,kb2) of 512B = lane*16B holding
// {kb=2*kb2 (8B: reg0,reg1), kb=2*kb2+1 (8B)} -> warp LDS.128 is sequential.
// ---------------------------------------------------------------------------
__global__ void prep_kernel(const float* __restrict__ conv_w,
                            const float* __restrict__ bg,
                            const float* __restrict__ bb,
                            const float* __restrict__ bm,
                            const float* __restrict__ bv,
                            const void*  __restrict__ pa1)
{
    int idx = blockIdx.x * blockDim.x + threadIdx.x;

    if (idx == 0) {
        const int* p = (const int*)pa1;   // int64 perm -> zero high words
        g_idx64 = (p[1] == 0 && p[3] == 0 && p[5] == 0 && p[7] == 0) ? 1 : 0;
    }
    if (idx < 384) {                      // bias fold [bk][L][o]
        int o = idx & 63, L = (idx >> 6) % 3, bk = idx / 192;
        float sc = bg[idx] * rsqrtf(bv[idx] + EPS_);
        g_bias[bk][L * 64 + o] = bb[idx] - bm[idx] * sc;
    }
    if (idx < 36864) {
        int q = idx;
        int reg  = q & 1;  q >>= 1;
        int kbl  = q & 1;  q >>= 1;
        int lane = q & 31; q >>= 5;
        int kb2  = q & 1;  q >>= 1;
        int nb   = q & 7;  q >>= 3;
        int t    = q % 3;  q /= 3;
        int L    = q % 3;
        int bk   = q / 3;
        int kb   = kb2 * 2 + kbl;

        int n  = nb * 8 + (lane >> 2);                 // output channel
        int k0 = kb * 16 + reg * 8 + (lane & 3) * 2;   // input channel pair
        int bni = (bk * 3 + L) * 64 + n;
        float sc = bg[bni] * rsqrtf(bv[bni] + EPS_);

        float w0 = conv_w[(((size_t)(bk * 3 + L) * 64 + n) * 64 + (k0 + 0)) * 3 + t] * sc;
        float w1 = conv_w[(((size_t)(bk * 3 + L) * 64 + n) * 64 + (k0 + 1)) * 3 + t] * sc;
        g_wfrag[idx] = packh(w0, w1);
    }
}

// ---------------------------------------------------------------------------
// Fused block: gather -> 3 x (mma.sync conv + BN + act) -> residual -> scatter
// One CTA = 250 output points (256-row buffer), 256 threads, 8 warps x M=32.
// Single-pass fp16, 2 CTAs/SM. b0 holds gathered x for the whole kernel
// (L1 writes in place into b1), so the residual comes from SMEM, not gmem.
// ---------------------------------------------------------------------------
template<bool INF16, bool OUTF16>
__global__ void __launch_bounds__(256, 2)
mc_block_kernel(const void* __restrict__ xinv,
                const void*  __restrict__ pav,
                void* __restrict__ outv,
                int bk)
{
    extern __shared__ uint8_t smem[];
    const uint32_t sbase = smem_u32(smem);
    const int tid = threadIdx.x, wid = tid >> 5, lane = tid & 31;
    const int b = blockIdx.y;
    const int ts = blockIdx.x * T_;
    const bool is64 = (g_idx64 != 0);
    const int*       pa32 = (const int*)pav;
    const long long* pa64 = (const long long*)pav;
    const float*  xf = (const float*)xinv;
    const __half* xh = (const __half*)xinv;

    if (tid < 192) ((float*)(smem + SM_BIAS))[tid] = g_bias[bk][tid];

    // ---- stage layer-0 weight fragments (24KB) via cp.async (overlaps gather) ----
    {
        const uint8_t* src = (const uint8_t*)g_wfrag + (size_t)(bk * 3) * WBYTES;
        #pragma unroll
        for (int i = 0; i < 6; ++i) {
            int e = tid + i * 256;
            CPA16(sbase + SM_W + e * 16, src + (size_t)e * 16);
        }
        CPA_COMMIT();
    }

    // ---- gather 256 rows (points ts-3 .. ts+252) into b0, fp16 ----
    {
        const int r = tid;                 // one thread per row
        int gp = ts - 3 + r;
        bool ok = (gp >= 0) && (gp < N_);
        long long prow = 0;
        if (ok) prow = is64 ? pa64[(size_t)b * N_ + gp]
                            : (long long)pa32[(size_t)b * N_ + gp];
        uint8_t* b0 = smem + SM_BUF;
        if (INF16) {
            const uint4* src = (const uint4*)(xh + ((size_t)b * N_ + (size_t)prow) * 64);
            #pragma unroll
            for (int i = 0; i < 8; ++i) {
                uint4 v = ok ? src[i] : make_uint4(0u, 0u, 0u, 0u);
                *(uint4*)(b0 + (uint32_t)(r * ROWSTRIDE + i * 16)) = v;
            }
        } else {
            const float4* src = (const float4*)(xf + ((size_t)b * N_ + (size_t)prow) * 64);
            #pragma unroll
            for (int i = 0; i < 16; ++i) {
                float4 v = ok ? src[i] : make_float4(0.f, 0.f, 0.f, 0.f);
                uint32_t off = (uint32_t)(r * ROWSTRIDE + i * 8);
                *(uint2*)(b0 + off) = make_uint2(packh(v.x, v.y), packh(v.z, v.w));
            }
        }
    }

    CPA_WAIT0();
    __syncthreads();

    // A-operand ldmatrix row offsets: [slab][tap], rows clamped to [0,255]
    uint32_t aoff[2][3];
    #pragma unroll
    for (int s2 = 0; s2 < 2; ++s2)
        #pragma unroll
        for (int t = 0; t < 3; ++t) {
            int rr = wid * 32 + s2 * 16 + t - 1 + (lane & 15);
            rr = rr < 0 ? 0 : (rr > 255 ? 255 : rr);
            aoff[s2][t] = (uint32_t)(rr * ROWSTRIDE) + ((lane >> 4) * 16);
        }

    #pragma unroll
    for (int L = 0; L < 3; ++L) {
        const int inp = (L == 0) ? 0 : 1;          // L0:b0(x), L1:b1(h1), L2:b1(h2)
        const uint32_t inB = sbase + SM_BUF + (uint32_t)inp * BUFBYTES;
        const uint32_t wl = sbase + SM_W + (uint32_t)lane * 16;

        float d[2][8][4];
        #pragma unroll
        for (int s2 = 0; s2 < 2; ++s2)
            #pragma unroll
            for (int nb = 0; nb < 8; ++nb)
                #pragma unroll
                for (int j = 0; j < 4; ++j) d[s2][nb][j] = 0.f;

        #pragma unroll
        for (int t = 0; t < 3; ++t) {
            #pragma unroll
            for (int kb2 = 0; kb2 < 2; ++kb2) {
                uint32_t a00[4], a10[4], a01[4], a11[4];
                LDSM4(a00, inB + aoff[0][t] + (kb2 * 2 + 0) * 32);
                LDSM4(a10, inB + aoff[1][t] + (kb2 * 2 + 0) * 32);
                LDSM4(a01, inB + aoff[0][t] + (kb2 * 2 + 1) * 32);
                LDSM4(a11, inB + aoff[1][t] + (kb2 * 2 + 1) * 32);

                #pragma unroll
                for (int nb = 0; nb < 8; ++nb) {
                    uint4 bq;                 // {kb even: x,y | kb odd: z,w}
                    LDS128(bq, wl + (uint32_t)(((t * 8 + nb) * 2 + kb2) * 512));
                    mma_f16(d[0][nb], a00, bq.x, bq.y);
                    mma_f16(d[1][nb], a10, bq.x, bq.y);
                    mma_f16(d[0][nb], a01, bq.z, bq.w);
                    mma_f16(d[1][nb], a11, bq.z, bq.w);
                }
            }
        }

        // ---- epilogue ----
        const float* bias = (const float*)(smem + SM_BIAS) + L * 64;

        if (L < 2) {
            // L0 writes h1 into b1; L1 writes h2 into b1 IN PLACE (all reads of
            // b1 completed by every warp before any write, enforced by barrier).
            if (L == 1) __syncthreads();
            uint8_t* ob = smem + SM_BUF + BUFBYTES;        // b1
            #pragma unroll
            for (int s2 = 0; s2 < 2; ++s2) {
                #pragma unroll
                for (int rh = 0; rh < 2; ++rh) {
                    const int r = wid * 32 + s2 * 16 + rh * 8 + (lane >> 2);
                    const int gp = ts - 3 + r;
                    const bool valid = (r >= L + 1) && (r <= 254 - L) && (gp >= 0) && (gp < N_);
                    #pragma unroll
                    for (int nb = 0; nb < 8; ++nb) {
                        const int c0 = nb * 8 + (lane & 3) * 2;
                        float v0 = valid ? fmaxf(d[s2][nb][rh * 2 + 0] + bias[c0], 0.f) : 0.f;
                        float v1 = valid ? fmaxf(d[s2][nb][rh * 2 + 1] + bias[c0 + 1], 0.f) : 0.f;
                        *(uint32_t*)(ob + (uint32_t)(r * ROWSTRIDE + c0 * 2)) = packh(v0, v1);
                    }
                }
            }
            __syncthreads();     // epi visible + W buffer free
            {                    // stage next layer's weights (24KB)
                const uint8_t* src = (const uint8_t*)g_wfrag + (size_t)(bk * 3 + L + 1) * WBYTES;
                #pragma unroll
                for (int i = 0; i < 6; ++i) {
                    int e = tid + i * 256;
                    CPA16(sbase + SM_W + e * 16, src + (size_t)e * 16);
                }
                CPA_COMMIT();
                CPA_WAIT0();
            }
            __syncthreads();
        } else {
            // residual from SMEM b0 (preserved x) + ReLU + permuted scatter
            const uint8_t* rb = smem + SM_BUF;             // b0
            #pragma unroll
            for (int s2 = 0; s2 < 2; ++s2) {
                #pragma unroll
                for (int rh = 0; rh < 2; ++rh) {
                    const int r = wid * 32 + s2 * 16 + rh * 8 + (lane >> 2);
                    const int gp = ts - 3 + r;
                    if (r >= 3 && r <= 252 && gp < N_) {
                        long long prow = is64 ? pa64[(size_t)b * N_ + gp]
                                              : (long long)pa32[(size_t)b * N_ + gp];
                        const size_t rowbase = ((size_t)b * N_ + (size_t)prow) * 64;
                        #pragma unroll
                        for (int nb = 0; nb < 8; ++nb) {
                            const int c0 = nb * 8 + (lane & 3) * 2;
                            uint32_t u = *(const uint32_t*)(rb + (uint32_t)(r * ROWSTRIDE + c0 * 2));
                            __half2 h2v = *(__half2*)&u;
                            float o0 = fmaxf(__low2float(h2v)  + d[s2][nb][rh * 2 + 0] + bias[c0], 0.f);
                            float o1 = fmaxf(__high2float(h2v) + d[s2][nb][rh * 2 + 1] + bias[c0 + 1], 0.f);
                            if (OUTF16) {
                                *(uint32_t*)((__half*)outv + rowbase + c0) = packh(o0, o1);
                            } else {
                                *(float2*)((float*)outv + rowbase + c0) = make_float2(o0, o1);
                            }
                        }
                    }
                }
            }
        }
    }
}

// ---------------------------------------------------------------------------
extern "C" void kernel_launch(void* const* d_in, const int* in_sizes, int n_in,
                              void* d_out, int out_size)
{
    const float* x      = (const float*)d_in[0];
    const void*  pa1    = d_in[1];
    // d_in[2] = idx_re_1 (unused: re ∘ pa = id, scatter uses pa)
    const void*  pa2    = d_in[3];
    // d_in[4] = idx_re_2 (unused)
    const float* conv_w = (const float*)d_in[5];
    const float* bg     = (const float*)d_in[6];
    const float* bb     = (const float*)d_in[7];
    const float* bm     = (const float*)d_in[8];
    const float* bv     = (const float*)d_in[9];
    float* out = (float*)d_out;

    cudaFuncSetAttribute(mc_block_kernel<false, true>,
                         cudaFuncAttributeMaxDynamicSharedMemorySize, SM_TOTAL);
    cudaFuncSetAttribute(mc_block_kernel<true, false>,
                         cudaFuncAttributeMaxDynamicSharedMemorySize, SM_TOTAL);

    void* tmpp = nullptr;
    cudaGetSymbolAddress(&tmpp, g_tmp);

    prep_kernel<<<(36864 + 255) / 256, 256>>>(conv_w, bg, bb, bm, bv, pa1);

    dim3 grid(NTILE, B_);
    mc_block_kernel<false, true><<<grid, 256, SM_TOTAL>>>(x, pa1, tmpp, 0);
    mc_block_kernel<true, false><<<grid, 256, SM_TOTAL>>>(tmpp, pa2, out, 1);
}